// round 8
// baseline (speedup 1.0000x reference)
#include <cuda_runtime.h>
#include <cuda_bf16.h>
#include <cstdint>

#define N_   16384
#define D_   2048
#define P_   256
#define NB   32
#define NL   100
#define NSEG (NB*NL)
#define NST  3          // pipeline stages

#define SA_  (6.5f/127.0f)
#define SB_  (0.125f/127.0f)

// ---------------- scratch globals (no allocations allowed) -------------------
__device__ int8_t        g_w1d1[256 * D_];  // W1 digit 1
__device__ int8_t        g_w1d2[256 * D_];  // W1 digit 2
__device__ __nv_bfloat16 g_w2h [256 * D_];  // W2 bf16 hi
__device__ float g_sumx[NSEG * D_];         // exact fp32 segsum of x
__device__ float g_mpart[4 * NSEG * P_];    // K-split partials of segsum@W2^T
__device__ float g_sum_bl2[NSEG * P_];
__device__ float g_sum_b2 [NB   * P_];
__device__ float g_M[NSEG * P_];
__device__ float g_bias[P_];
__device__ int   g_cnt[NSEG];
__device__ int   g_seg[N_];
__device__ int   g_bstart[NB + 1];
__device__ int   g_is64;

// ---------------- PTX helpers ------------------------------------------------
__device__ __forceinline__ uint32_t smem_u32(const void* p) {
    uint32_t a;
    asm("{ .reg .u64 t; cvta.to.shared.u64 t, %1; cvt.u32.u64 %0, t; }" : "=r"(a) : "l"(p));
    return a;
}
__device__ __forceinline__ void cp16(uint32_t dst, const void* src) {
    asm volatile("cp.async.cg.shared.global [%0], [%1], 16;" :: "r"(dst), "l"(src));
}
#define CP_COMMIT() asm volatile("cp.async.commit_group;" ::: "memory")
#define CP_WAIT1()  asm volatile("cp.async.wait_group 1;"  ::: "memory")
#define CP_WAIT0()  asm volatile("cp.async.wait_group 0;"  ::: "memory")

__device__ __forceinline__ uint32_t swz(uint32_t o) {   // 64B-row swizzle
    return o ^ ((o >> 3) & 0x30);
}
__device__ __forceinline__ void ldm4(uint32_t addr, uint32_t& r0, uint32_t& r1,
                                     uint32_t& r2, uint32_t& r3) {
    asm volatile("ldmatrix.sync.aligned.m8n8.x4.shared.b16 {%0,%1,%2,%3}, [%4];"
                 : "=r"(r0), "=r"(r1), "=r"(r2), "=r"(r3) : "r"(addr));
}
__device__ __forceinline__ void mma16816(float* d, const uint32_t* a,
                                         const uint32_t* b) {
    asm volatile(
        "mma.sync.aligned.m16n8k16.row.col.f32.bf16.bf16.f32 "
        "{%0,%1,%2,%3}, {%4,%5,%6,%7}, {%8,%9}, {%0,%1,%2,%3};"
        : "+f"(d[0]), "+f"(d[1]), "+f"(d[2]), "+f"(d[3])
        : "r"(a[0]), "r"(a[1]), "r"(a[2]), "r"(a[3]), "r"(b[0]), "r"(b[1]));
}
__device__ __forceinline__ void imma16832(int* d, const uint32_t* a,
                                          const uint32_t* b) {
    asm volatile(
        "mma.sync.aligned.m16n8k32.row.col.s32.s8.s8.s32 "
        "{%0,%1,%2,%3}, {%4,%5,%6,%7}, {%8,%9}, {%0,%1,%2,%3};"
        : "+r"(d[0]), "+r"(d[1]), "+r"(d[2]), "+r"(d[3])
        : "r"(a[0]), "r"(a[1]), "r"(a[2]), "r"(a[3]), "r"(b[0]), "r"(b[1]));
}
__device__ __forceinline__ void sts16(uint32_t addr, uint32_t r0, uint32_t r1,
                                      uint32_t r2, uint32_t r3) {
    asm volatile("st.shared.v4.b32 [%0], {%1,%2,%3,%4};"
                 :: "r"(addr), "r"(r0), "r"(r1), "r"(r2), "r"(r3) : "memory");
}

// ---------------- digit / bf16 packers ---------------------------------------
__device__ __forceinline__ void dig1(float v, float invS, int& q1, int& q2) {
    float t = fmaxf(-127.0f, fminf(127.0f, v * invS));
    q1 = __float2int_rn(t);
    q2 = __float2int_rn((t - (float)q1) * 254.0f);
}
__device__ __forceinline__ uint32_t pack4(int a, int b, int c, int d) {
    return (a & 0xFF) | ((b & 0xFF) << 8) | ((c & 0xFF) << 16) | ((uint32_t)d << 24);
}
__device__ __forceinline__ void dig4(float4 v, float invS, uint32_t& d1, uint32_t& d2) {
    int a1, a2, b1, b2, c1, c2, e1, e2;
    dig1(v.x, invS, a1, a2); dig1(v.y, invS, b1, b2);
    dig1(v.z, invS, c1, c2); dig1(v.w, invS, e1, e2);
    d1 = pack4(a1, b1, c1, e1);
    d2 = pack4(a2, b2, c2, e2);
}
__device__ __forceinline__ void packh4(float4 v, uint32_t& h0, uint32_t& h1) {
    __nv_bfloat162 p0(__float2bfloat16(v.x), __float2bfloat16(v.y));
    __nv_bfloat162 p1(__float2bfloat16(v.z), __float2bfloat16(v.w));
    h0 = *(uint32_t*)&p0; h1 = *(uint32_t*)&p1;
}

// ---------------- dtype detection + count zeroing ----------------------------
__global__ void k_detect(const int* label, const int* lb) {
    __shared__ int nz_la, nz_lb;
    int t = threadIdx.x;
    if (t == 0) { nz_la = 0; nz_lb = 0; }
    __syncthreads();
    if (t < 64) {
        int w = 2 * (t * 128) + 1;
        if (label[w] != 0) atomicOr(&nz_la, 1);
        if (lb[w]    != 0) atomicOr(&nz_lb, 1);
    }
    __syncthreads();
    if (t == 0) g_is64 = (nz_la ? 0 : 1) | (nz_lb ? 0 : 2);
    for (int i = t; i < NSEG; i += blockDim.x) g_cnt[i] = 0;
}
__device__ __forceinline__ int ld_idx(const int* p, int i, bool is64) {
    return is64 ? p[2 * i] : p[i];
}

// ---------------- seg ids, counts, batch boundaries --------------------------
__global__ void k_prep(const int* label, const int* lb) {
    bool la64 = (g_is64 & 1) != 0, lb64 = (g_is64 & 2) != 0;
    int i = blockIdx.x * blockDim.x + threadIdx.x;
    if (i < N_) {
        int la = ld_idx(label, i, la64);
        int b  = ld_idx(lb,    i, lb64);
        int s  = b * NL + la;
        g_seg[i] = s;
        atomicAdd(&g_cnt[s], 1);
    }
    if (blockIdx.x == 0 && threadIdx.x <= NB) {
        int target = threadIdx.x;
        int lo = 0, hi = N_;
        while (lo < hi) {
            int mid = (lo + hi) >> 1;
            if (ld_idx(lb, mid, lb64) < target) lo = mid + 1; else hi = mid;
        }
        g_bstart[target] = lo;
    }
}

// ---------------- weight conversion: W1 -> int8 digits, W2 -> bf16 hi --------
__global__ void k_convw(const float* __restrict__ W1, const float* __restrict__ W2,
                        const float* __restrict__ b1, const float* __restrict__ b2) {
    int i = blockIdx.x * blockDim.x + threadIdx.x;   // float4 index over 512x2048
    int e = i * 4;
    int row = e >> 11;
    int col = e & 2047;
    if (row < 256) {
        float4 v = *(const float4*)(W1 + (size_t)row * D_ + col);
        uint32_t d1, d2;
        dig4(v, 1.0f / SB_, d1, d2);
        ((uint32_t*)g_w1d1)[i] = d1;
        ((uint32_t*)g_w1d2)[i] = d2;
    } else {
        float4 v = *(const float4*)(W2 + (size_t)(row - 256) * D_ + col);
        uint32_t h0, h1;
        packh4(v, h0, h1);
        ((uint2*)g_w2h)[i - 131072] = make_uint2(h0, h1);
    }
    if (blockIdx.x == 0 && threadIdx.x < P_)
        g_bias[threadIdx.x] = b1[threadIdx.x] + b2[threadIdx.x];
}

// ---------------- exact fp32 segment sums of x -------------------------------
__global__ void k_segsum(const float* __restrict__ x) {
    __shared__ float acc[NL * 64];      // 25.6 KB
    int b  = blockIdx.y;
    int c0 = blockIdx.x * 64;
    int t  = threadIdx.x;
    for (int i = t; i < NL * 64; i += 256) acc[i] = 0.0f;
    __syncthreads();
    int r0 = g_bstart[b], r1 = g_bstart[b + 1];
    int col = t & 63, rs = t >> 6;
    for (int r = r0 + rs; r < r1; r += 4) {
        int lab = g_seg[r] - b * NL;
        atomicAdd(&acc[lab * 64 + col], x[(size_t)r * D_ + c0 + col]);
    }
    __syncthreads();
    for (int i = t; i < NL * 64; i += 256) {
        int l = i >> 6, c = i & 63;
        g_sumx[(size_t)(b * NL + l) * D_ + c0 + c] = acc[i];
    }
}

// =============== main GEMM: out = x @ W1^T (int8 3-term) + M[seg] ============
// CTA 64(M) x 128(N), K-tile 64 elems (64B rows), 256 thr, warp grid 2x4.
// Stage: A_d1 4K | A_d2 4K | B_d1 8K | B_d2 8K = 24KB. NST=3 -> 72KB.
#define STAGE_B 24576
#define SMEM_REQ (NST * STAGE_B)
#define KTN_MAIN 32

__device__ __forceinline__ void ldgA8(const float* __restrict__ Arows, int kt,
                                      int tid, float4* areg) {
    int row = tid >> 2, h = tid & 3;                 // 4 thr/row, 16 floats each
    const float4* p = (const float4*)(Arows + (size_t)row * D_ + (kt << 6) + h * 16);
    areg[0] = p[0]; areg[1] = p[1]; areg[2] = p[2]; areg[3] = p[3];
}
__device__ __forceinline__ void stsA8(uint32_t sg, int tid, const float4* areg) {
    int row = tid >> 2, h = tid & 3;
    uint32_t d1[4], d2[4];
    dig4(areg[0], 1.0f / SA_, d1[0], d2[0]);
    dig4(areg[1], 1.0f / SA_, d1[1], d2[1]);
    dig4(areg[2], 1.0f / SA_, d1[2], d2[2]);
    dig4(areg[3], 1.0f / SA_, d1[3], d2[3]);
    uint32_t o = swz(row * 64 + h * 16);
    sts16(sg + o,        d1[0], d1[1], d1[2], d1[3]);
    sts16(sg + 4096 + o, d2[0], d2[1], d2[2], d2[3]);
}
__device__ __forceinline__ void ldB8(int n0, int kt, uint32_t sg, int tid) {
    int k0 = kt << 6;
    const char* gB1 = (const char*)g_w1d1 + (size_t)n0 * D_ + k0;
    const char* gB2 = (const char*)g_w1d2 + (size_t)n0 * D_ + k0;
    #pragma unroll
    for (int i = 0; i < 2; i++) {
        int idx = i * 256 + tid;
        int row = idx >> 2, c = idx & 3;
        uint32_t off = swz(row * 64 + c * 16);
        cp16(sg + 8192  + off, gB1 + (size_t)row * D_ + c * 16);
        cp16(sg + 16384 + off, gB2 + (size_t)row * D_ + c * 16);
    }
}

__global__ void __launch_bounds__(256, 2) k_gemm(const float* __restrict__ x,
                                                 float* __restrict__ out) {
    extern __shared__ __align__(128) char smem[];
    uint32_t sbase = smem_u32(smem);
    int tid = threadIdx.x, lane = tid & 31, wid = tid >> 5;
    int wm = wid & 1, wn = wid >> 1;                 // warp grid 2(M) x 4(N)
    int n0 = blockIdx.x * 128, m0 = blockIdx.y * 64;

    int d11[2][4][4], dxx[2][4][4];
    #pragma unroll
    for (int i = 0; i < 2; i++)
        #pragma unroll
        for (int j = 0; j < 4; j++)
            #pragma unroll
            for (int k = 0; k < 4; k++) { d11[i][j][k] = 0; dxx[i][j][k] = 0; }

    float4 areg[4];
    ldgA8(x + (size_t)m0 * D_, 0, tid, areg);
    stsA8(sbase, tid, areg);
    ldB8(n0, 0, sbase, tid); CP_COMMIT();
    ldgA8(x + (size_t)m0 * D_, 1, tid, areg);
    ldB8(n0, 1, sbase + STAGE_B, tid); CP_COMMIT();

    uint32_t aoff[2], boff[2];
    #pragma unroll
    for (int s = 0; s < 2; s++) {
        int arow = wm * 32 + (lane & 15);
        int acol = s * 32 + (lane >> 4) * 16;
        aoff[s] = swz(arow * 64 + acol);
        int brow = wn * 32 + ((lane >> 4) & 1) * 8 + (lane & 7);
        int bcol = s * 32 + ((lane >> 3) & 1) * 16;
        boff[s] = swz(brow * 64 + bcol);
    }

    for (int kt = 0; kt < KTN_MAIN; kt++) {
        CP_WAIT1();
        __syncthreads();
        if (kt + 1 < KTN_MAIN)
            stsA8(sbase + ((kt + 1) % NST) * STAGE_B, tid, areg);
        if (kt + 2 < KTN_MAIN) {
            ldgA8(x + (size_t)m0 * D_, kt + 2, tid, areg);
            ldB8(n0, kt + 2, sbase + ((kt + 2) % NST) * STAGE_B, tid);
        }
        CP_COMMIT();

        uint32_t sA1 = sbase + (kt % NST) * STAGE_B;
        uint32_t sA2 = sA1 + 4096;
        uint32_t sB1 = sA1 + 8192;
        uint32_t sB2 = sA1 + 16384;
        #pragma unroll
        for (int s = 0; s < 2; s++) {
            uint32_t a[2][4], b1[4][2], b2[4][2];
            #pragma unroll
            for (int f = 0; f < 2; f++)
                ldm4(sA1 + f * 1024 + aoff[s], a[f][0], a[f][1], a[f][2], a[f][3]);
            #pragma unroll
            for (int p = 0; p < 2; p++)
                ldm4(sB1 + p * 1024 + boff[s],
                     b1[2 * p][0], b1[2 * p][1], b1[2 * p + 1][0], b1[2 * p + 1][1]);
            #pragma unroll
            for (int mf = 0; mf < 2; mf++)
                #pragma unroll
                for (int nf = 0; nf < 4; nf++)
                    imma16832(d11[mf][nf], a[mf], b1[nf]);
            #pragma unroll
            for (int p = 0; p < 2; p++)
                ldm4(sB2 + p * 1024 + boff[s],
                     b2[2 * p][0], b2[2 * p][1], b2[2 * p + 1][0], b2[2 * p + 1][1]);
            #pragma unroll
            for (int mf = 0; mf < 2; mf++)
                #pragma unroll
                for (int nf = 0; nf < 4; nf++)
                    imma16832(dxx[mf][nf], a[mf], b2[nf]);
            #pragma unroll
            for (int f = 0; f < 2; f++)
                ldm4(sA2 + f * 1024 + aoff[s], a[f][0], a[f][1], a[f][2], a[f][3]);
            #pragma unroll
            for (int mf = 0; mf < 2; mf++)
                #pragma unroll
                for (int nf = 0; nf < 4; nf++)
                    imma16832(dxx[mf][nf], a[mf], b1[nf]);
        }
    }
    CP_WAIT0();

    const float RS = SA_ * SB_;
    #pragma unroll
    for (int mf = 0; mf < 2; mf++) {
        int r0 = m0 + wm * 32 + mf * 16 + (lane >> 2);
        int s0 = g_seg[r0], s1 = g_seg[r0 + 8];
        #pragma unroll
        for (int nf = 0; nf < 4; nf++) {
            int c = n0 + wn * 32 + nf * 8 + (lane & 3) * 2;
            float2 M0 = *(const float2*)(g_M + (size_t)s0 * P_ + c);
            float2 M1 = *(const float2*)(g_M + (size_t)s1 * P_ + c);
            float2 v0, v1;
            v0.x = RS * ((float)d11[mf][nf][0] + (float)dxx[mf][nf][0] * (1.0f/254.0f)) + M0.x;
            v0.y = RS * ((float)d11[mf][nf][1] + (float)dxx[mf][nf][1] * (1.0f/254.0f)) + M0.y;
            v1.x = RS * ((float)d11[mf][nf][2] + (float)dxx[mf][nf][2] * (1.0f/254.0f)) + M1.x;
            v1.y = RS * ((float)d11[mf][nf][3] + (float)dxx[mf][nf][3] * (1.0f/254.0f)) + M1.y;
            *(float2*)(out + (size_t)r0 * P_ + c)       = v0;
            *(float2*)(out + (size_t)(r0 + 8) * P_ + c) = v1;
        }
    }
}

// =============== mean GEMM: g_mpart[ks] = segsum_x @ W2^T (1-term bf16) ======
// CTA 64x128, BK=32 bf16 (64B rows), K-split 4 (512 each, 16 tiles).
#define MSTAGE_B 12288
#define MSMEM_REQ (NST * MSTAGE_B)

__device__ __forceinline__ void ldgA1(const float* __restrict__ Arows, int kt,
                                      int tid, float4* areg) {
    int row = tid >> 2, h = tid & 3;                 // 8 floats each
    const float4* p = (const float4*)(Arows + (size_t)row * D_ + (kt << 5) + h * 8);
    areg[0] = p[0]; areg[1] = p[1];
}
__device__ __forceinline__ void stsA1(uint32_t sg, int tid, const float4* areg) {
    int row = tid >> 2, h = tid & 3;
    uint32_t h0, h1, h2, h3;
    packh4(areg[0], h0, h1);
    packh4(areg[1], h2, h3);
    sts16(sg + swz(row * 64 + h * 16), h0, h1, h2, h3);
}
__device__ __forceinline__ void ldB1(const char* Bh, int kt, uint32_t sg, int tid) {
    int k0 = kt << 6;   // bytes
    #pragma unroll
    for (int i = 0; i < 2; i++) {
        int idx = i * 256 + tid;
        int row = idx >> 2, c = idx & 3;
        uint32_t off = swz(row * 64 + c * 16);
        cp16(sg + 4096 + off, Bh + (size_t)row * (D_ * 2) + k0 + c * 16);
    }
}

__global__ void __launch_bounds__(256, 3) k_mgemm() {
    extern __shared__ __align__(128) char smem[];
    uint32_t sbase = smem_u32(smem);
    int tid = threadIdx.x, lane = tid & 31, wid = tid >> 5;
    int wm = wid & 1, wn = wid >> 1;
    int n0 = blockIdx.x * 128, m0 = blockIdx.y * 64, ks = blockIdx.z;
    const float* Arows = g_sumx + (size_t)m0 * D_ + ks * 512;
    const char*  Bh    = (const char*)g_w2h + (size_t)n0 * (D_ * 2) + ks * 1024;
    float* dst = g_mpart + (size_t)ks * NSEG * P_ + (size_t)m0 * P_ + n0;
    const int ktn = 16;

    float d[2][4][4];
    #pragma unroll
    for (int i = 0; i < 2; i++)
        #pragma unroll
        for (int j = 0; j < 4; j++)
            #pragma unroll
            for (int k = 0; k < 4; k++) d[i][j][k] = 0.0f;

    float4 areg[2];
    ldgA1(Arows, 0, tid, areg);
    stsA1(sbase, tid, areg);
    ldB1(Bh, 0, sbase, tid); CP_COMMIT();
    ldgA1(Arows, 1, tid, areg);
    ldB1(Bh, 1, sbase + MSTAGE_B, tid); CP_COMMIT();

    uint32_t aoff[2], boff[2];
    #pragma unroll
    for (int s = 0; s < 2; s++) {
        int arow = wm * 32 + (lane & 15);
        int acol = s * 32 + (lane >> 4) * 16;
        aoff[s] = swz(arow * 64 + acol);
        int brow = wn * 32 + ((lane >> 4) & 1) * 8 + (lane & 7);
        int bcol = s * 32 + ((lane >> 3) & 1) * 16;
        boff[s] = swz(brow * 64 + bcol);
    }

    for (int kt = 0; kt < ktn; kt++) {
        CP_WAIT1();
        __syncthreads();
        if (kt + 1 < ktn)
            stsA1(sbase + ((kt + 1) % NST) * MSTAGE_B, tid, areg);
        if (kt + 2 < ktn) {
            ldgA1(Arows, kt + 2, tid, areg);
            ldB1(Bh, kt + 2, sbase + ((kt + 2) % NST) * MSTAGE_B, tid);
        }
        CP_COMMIT();

        uint32_t sA = sbase + (kt % NST) * MSTAGE_B;
        uint32_t sB = sA + 4096;
        #pragma unroll
        for (int s = 0; s < 2; s++) {
            uint32_t a[2][4], b[4][2];
            #pragma unroll
            for (int f = 0; f < 2; f++)
                ldm4(sA + f * 1024 + aoff[s], a[f][0], a[f][1], a[f][2], a[f][3]);
            #pragma unroll
            for (int p = 0; p < 2; p++)
                ldm4(sB + p * 1024 + boff[s],
                     b[2 * p][0], b[2 * p][1], b[2 * p + 1][0], b[2 * p + 1][1]);
            #pragma unroll
            for (int mf = 0; mf < 2; mf++)
                #pragma unroll
                for (int nf = 0; nf < 4; nf++)
                    mma16816(d[mf][nf], a[mf], b[nf]);
        }
    }
    CP_WAIT0();

    #pragma unroll
    for (int mf = 0; mf < 2; mf++) {
        #pragma unroll
        for (int nf = 0; nf < 4; nf++) {
            int r = wm * 32 + mf * 16 + (lane >> 2);
            int c = wn * 32 + nf * 8 + (lane & 3) * 2;
            *(float2*)(dst + (size_t)r * P_ + c)
                = make_float2(d[mf][nf][0], d[mf][nf][1]);
            *(float2*)(dst + (size_t)(r + 8) * P_ + c)
                = make_float2(d[mf][nf][2], d[mf][nf][3]);
        }
    }
}

// ---------------- reduce K-split parts ---------------------------------------
__global__ void k_mred() {
    int i = blockIdx.x * blockDim.x + threadIdx.x;
    float s = g_mpart[i] + g_mpart[NSEG * P_ + i]
            + g_mpart[2 * NSEG * P_ + i] + g_mpart[3 * NSEG * P_ + i];
    g_sum_bl2[i] = s;
}

// ---------------- per-batch sums from per-seg sums ---------------------------
__global__ void k_sumb() {
    int b = blockIdx.x, h = blockIdx.y;
    int col = h * 128 + threadIdx.x;
    const float* base = g_sum_bl2 + (size_t)(b * NL) * P_ + col;
    float acc = 0.0f;
    #pragma unroll 4
    for (int l = 0; l < NL; l++) acc += base[(size_t)l * P_];
    g_sum_b2[b * P_ + col] = acc;
}

// ---------------- per-segment output addend ----------------------------------
__global__ void k_minv() {
    int s = blockIdx.x, t = threadIdx.x;
    int b = s / NL;
    int cb = g_bstart[b + 1] - g_bstart[b];
    int d = cb - g_cnt[s];
    float inv = (d > 0) ? (1.0f / (float)d) : 0.0f;
    float m = (g_sum_b2[b * P_ + t] - g_sum_bl2[(size_t)s * P_ + t]) * inv;
    g_M[(size_t)s * P_ + t] = m + g_bias[t];
}

// ---------------- launch -----------------------------------------------------
extern "C" void kernel_launch(void* const* d_in, const int* in_sizes, int n_in,
                              void* d_out, int out_size) {
    const float* x     = (const float*)d_in[0];
    const int*   label = (const int*)  d_in[1];
    const int*   lb    = (const int*)  d_in[2];
    const float* W1_w  = (const float*)d_in[3];
    const float* W1_b  = (const float*)d_in[4];
    const float* W2_w  = (const float*)d_in[5];
    const float* W2_b  = (const float*)d_in[6];
    float* out = (float*)d_out;

    cudaFuncSetAttribute(k_gemm,  cudaFuncAttributeMaxDynamicSharedMemorySize, SMEM_REQ);
    cudaFuncSetAttribute(k_mgemm, cudaFuncAttributeMaxDynamicSharedMemorySize, MSMEM_REQ);

    k_convw<<<(512 * D_ / 4) / 256, 256>>>(W1_w, W2_w, W1_b, W2_b);
    k_detect<<<1, 256>>>(label, lb);
    k_prep<<<N_ / 256, 256>>>(label, lb);
    k_segsum<<<dim3(D_ / 64, NB), 256>>>(x);
    k_mgemm<<<dim3(2, NSEG / 64, 4), 256, MSMEM_REQ>>>();
    k_mred<<<(NSEG * P_) / 256, 256>>>();
    k_sumb<<<dim3(NB, 2), 128>>>();
    k_minv<<<NSEG, 256>>>();
    k_gemm<<<dim3(2, 256), 256, SMEM_REQ>>>(x, out);
}

// round 9
// speedup vs baseline: 2.8288x; 2.8288x over previous
#include <cuda_runtime.h>
#include <cuda_bf16.h>
#include <cstdint>

#define N_   16384
#define D_   2048
#define P_   256
#define NB   32
#define NL   100
#define NSEG (NB*NL)
#define NST  3          // pipeline stages

// ---------------- scratch globals (no allocations allowed) -------------------
__device__ __nv_bfloat16 g_bhi[512 * D_];   // [W1;W2] hi
__device__ __nv_bfloat16 g_blo[512 * D_];   // [W1;W2] lo (W2 half unused)
__device__ float g_sumx[NSEG * D_];         // exact fp32 segsum of x
__device__ float g_mpart[4 * NSEG * P_];    // K-split partials of segsum@W2^T
__device__ float g_sum_bl2[NSEG * P_];
__device__ float g_sum_b2 [NB   * P_];
__device__ float g_M[NSEG * P_];
__device__ float g_bias[P_];
__device__ int   g_cnt[NSEG];
__device__ int   g_seg[N_];
__device__ int   g_bstart[NB + 1];
__device__ int   g_is64;

// ---------------- PTX helpers ------------------------------------------------
__device__ __forceinline__ uint32_t smem_u32(const void* p) {
    uint32_t a;
    asm("{ .reg .u64 t; cvta.to.shared.u64 t, %1; cvt.u32.u64 %0, t; }" : "=r"(a) : "l"(p));
    return a;
}
__device__ __forceinline__ void cp16(uint32_t dst, const void* src) {
    asm volatile("cp.async.cg.shared.global [%0], [%1], 16;" :: "r"(dst), "l"(src));
}
#define CP_COMMIT() asm volatile("cp.async.commit_group;" ::: "memory")
#define CP_WAIT1()  asm volatile("cp.async.wait_group 1;"  ::: "memory")
#define CP_WAIT0()  asm volatile("cp.async.wait_group 0;"  ::: "memory")

__device__ __forceinline__ uint32_t swz(uint32_t o) {   // 64B-row swizzle
    return o ^ ((o >> 3) & 0x30);
}
__device__ __forceinline__ void ldm4(uint32_t addr, uint32_t& r0, uint32_t& r1,
                                     uint32_t& r2, uint32_t& r3) {
    asm volatile("ldmatrix.sync.aligned.m8n8.x4.shared.b16 {%0,%1,%2,%3}, [%4];"
                 : "=r"(r0), "=r"(r1), "=r"(r2), "=r"(r3) : "r"(addr));
}
__device__ __forceinline__ void mma16816(float* d, const uint32_t* a,
                                         const uint32_t* b) {
    asm volatile(
        "mma.sync.aligned.m16n8k16.row.col.f32.bf16.bf16.f32 "
        "{%0,%1,%2,%3}, {%4,%5,%6,%7}, {%8,%9}, {%0,%1,%2,%3};"
        : "+f"(d[0]), "+f"(d[1]), "+f"(d[2]), "+f"(d[3])
        : "r"(a[0]), "r"(a[1]), "r"(a[2]), "r"(a[3]), "r"(b[0]), "r"(b[1]));
}
__device__ __forceinline__ void sts16(uint32_t addr, uint32_t r0, uint32_t r1,
                                      uint32_t r2, uint32_t r3) {
    asm volatile("st.shared.v4.b32 [%0], {%1,%2,%3,%4};"
                 :: "r"(addr), "r"(r0), "r"(r1), "r"(r2), "r"(r3) : "memory");
}

// 4 floats -> hi bf16x2 pair + lo bf16x2 pair
__device__ __forceinline__ void pack_hilo(float4 v, uint32_t& h0, uint32_t& h1,
                                          uint32_t& l0, uint32_t& l1) {
    __nv_bfloat16 a = __float2bfloat16(v.x), b = __float2bfloat16(v.y);
    __nv_bfloat16 c = __float2bfloat16(v.z), d = __float2bfloat16(v.w);
    __nv_bfloat16 e = __float2bfloat16(v.x - __bfloat162float(a));
    __nv_bfloat16 f = __float2bfloat16(v.y - __bfloat162float(b));
    __nv_bfloat16 g = __float2bfloat16(v.z - __bfloat162float(c));
    __nv_bfloat16 h = __float2bfloat16(v.w - __bfloat162float(d));
    __nv_bfloat162 hh0(a, b), hh1(c, d), ll0(e, f), ll1(g, h);
    h0 = *(uint32_t*)&hh0; h1 = *(uint32_t*)&hh1;
    l0 = *(uint32_t*)&ll0; l1 = *(uint32_t*)&ll1;
}
__device__ __forceinline__ void packh4(float4 v, uint32_t& h0, uint32_t& h1) {
    __nv_bfloat162 p0(__float2bfloat16(v.x), __float2bfloat16(v.y));
    __nv_bfloat162 p1(__float2bfloat16(v.z), __float2bfloat16(v.w));
    h0 = *(uint32_t*)&p0; h1 = *(uint32_t*)&p1;
}

// ---------------- dtype detection + count zeroing ----------------------------
__global__ void k_detect(const int* label, const int* lb) {
    __shared__ int nz_la, nz_lb;
    int t = threadIdx.x;
    if (t == 0) { nz_la = 0; nz_lb = 0; }
    __syncthreads();
    if (t < 64) {
        int w = 2 * (t * 128) + 1;
        if (label[w] != 0) atomicOr(&nz_la, 1);
        if (lb[w]    != 0) atomicOr(&nz_lb, 1);
    }
    __syncthreads();
    if (t == 0) g_is64 = (nz_la ? 0 : 1) | (nz_lb ? 0 : 2);
    for (int i = t; i < NSEG; i += blockDim.x) g_cnt[i] = 0;
}
__device__ __forceinline__ int ld_idx(const int* p, int i, bool is64) {
    return is64 ? p[2 * i] : p[i];
}

// ---------------- seg ids, counts, batch boundaries --------------------------
__global__ void k_prep(const int* label, const int* lb) {
    bool la64 = (g_is64 & 1) != 0, lb64 = (g_is64 & 2) != 0;
    int i = blockIdx.x * blockDim.x + threadIdx.x;
    if (i < N_) {
        int la = ld_idx(label, i, la64);
        int b  = ld_idx(lb,    i, lb64);
        int s  = b * NL + la;
        g_seg[i] = s;
        atomicAdd(&g_cnt[s], 1);
    }
    if (blockIdx.x == 0 && threadIdx.x <= NB) {
        int target = threadIdx.x;
        int lo = 0, hi = N_;
        while (lo < hi) {
            int mid = (lo + hi) >> 1;
            if (ld_idx(lb, mid, lb64) < target) lo = mid + 1; else hi = mid;
        }
        g_bstart[target] = lo;
    }
}

// ---------------- weight hi/lo conversion ------------------------------------
__global__ void k_convw(const float* __restrict__ W1, const float* __restrict__ W2,
                        const float* __restrict__ b1, const float* __restrict__ b2) {
    int i = blockIdx.x * blockDim.x + threadIdx.x;   // float4 index over 512x2048
    int e = i * 4;
    int row = e >> 11;
    int col = e & 2047;
    const float* src = (row < 256) ? (W1 + (size_t)row * D_ + col)
                                   : (W2 + (size_t)(row - 256) * D_ + col);
    float4 v = *(const float4*)src;
    uint32_t h0, h1, l0, l1;
    pack_hilo(v, h0, h1, l0, l1);
    ((uint2*)g_bhi)[i] = make_uint2(h0, h1);
    ((uint2*)g_blo)[i] = make_uint2(l0, l1);
    if (blockIdx.x == 0 && threadIdx.x < P_)
        g_bias[threadIdx.x] = b1[threadIdx.x] + b2[threadIdx.x];
}

// ---------------- exact fp32 segment sums of x (atomic-free) ------------------
// grid (D/64 chunks, NB batches), 256 thr = 4 row-streams x 64 cols.
// Each stream owns a private acc[100][64] -> no atomics, plain smem RMW.
#define SEG_SMEM (4 * NL * 64 * 4)          // 102400 B
__global__ void k_segsum(const float* __restrict__ x) {
    extern __shared__ float sacc[];         // [4][NL][64]
    int b  = blockIdx.y;
    int c0 = blockIdx.x * 64;
    int t  = threadIdx.x;
    int col = t & 63, rs = t >> 6;
    float* acc = sacc + rs * (NL * 64);
    for (int i = t; i < 4 * NL * 64; i += 256) sacc[i] = 0.0f;
    __syncthreads();
    int r0 = g_bstart[b], r1 = g_bstart[b + 1];
    for (int r = r0 + rs; r < r1; r += 4) {
        int lab = g_seg[r] - b * NL;
        acc[lab * 64 + col] += x[(size_t)r * D_ + c0 + col];
    }
    __syncthreads();
    for (int i = t; i < NL * 64; i += 256) {
        int l = i >> 6, c = i & 63;
        float s = sacc[i] + sacc[NL * 64 + i] + sacc[2 * NL * 64 + i]
                + sacc[3 * NL * 64 + i];
        g_sumx[(size_t)(b * NL + l) * D_ + c0 + c] = s;
    }
}

// =============== main GEMM: out = x @ W1^T (3-term bf16) + M[seg] ============
// CTA tile 64(M) x 128(N), BK=32, 256 threads, warp grid 2x4 (tile 32x32).
// Stage: A_hi 4K | A_lo 4K | B_hi 8K | B_lo 8K = 24KB.  NST=3 -> 72KB.
#define STAGE_B 24576
#define SMEM_REQ (NST * STAGE_B)

__device__ __forceinline__ void ldgA(const float* __restrict__ Arows, int kt,
                                     int tid, float4* areg) {
    int row = tid >> 2, h = tid & 3;                 // 4 thr/row, 8 floats each
    const float4* p = (const float4*)(Arows + (size_t)row * D_ + (kt << 5) + h * 8);
    areg[0] = p[0]; areg[1] = p[1];
}
__device__ __forceinline__ void stsA(uint32_t sg, int tid, const float4* areg) {
    int row = tid >> 2, h = tid & 3;
    uint32_t h0a, h1a, l0a, l1a, h0b, h1b, l0b, l1b;
    pack_hilo(areg[0], h0a, h1a, l0a, l1a);
    pack_hilo(areg[1], h0b, h1b, l0b, l1b);
    uint32_t o = swz(row * 64 + h * 16);
    sts16(sg + o,        h0a, h1a, h0b, h1b);        // A_hi
    sts16(sg + 4096 + o, l0a, l1a, l0b, l1b);        // A_lo
}
__device__ __forceinline__ void ldB(const __nv_bfloat16* Bh, const __nv_bfloat16* Bl,
                                    int kt, uint32_t sg, int tid) {
    int k0 = kt << 5;
    const char* gBh = (const char*)(Bh + k0);
    const char* gBl = (const char*)(Bl + k0);
    #pragma unroll
    for (int i = 0; i < 2; i++) {
        int idx = i * 256 + tid;
        int row = idx >> 2, c = idx & 3;
        uint32_t off = swz(row * 64 + c * 16);
        cp16(sg + 8192  + off, gBh + (size_t)row * (D_ * 2) + c * 16);
        cp16(sg + 16384 + off, gBl + (size_t)row * (D_ * 2) + c * 16);
    }
}

__global__ void __launch_bounds__(256, 3) k_gemm(const float* __restrict__ x,
                                                 float* __restrict__ out) {
    extern __shared__ __align__(128) char smem[];
    uint32_t sbase = smem_u32(smem);
    int tid = threadIdx.x, lane = tid & 31, wid = tid >> 5;
    int wm = wid & 1, wn = wid >> 1;                 // warp grid 2(M) x 4(N)
    int n0 = blockIdx.x * 128, m0 = blockIdx.y * 64;
    const float* Arows = x + (size_t)m0 * D_;
    const __nv_bfloat16* Bh = g_bhi + (size_t)n0 * D_;
    const __nv_bfloat16* Bl = g_blo + (size_t)n0 * D_;
    const int ktn = 64;

    float d[2][4][4];
    #pragma unroll
    for (int i = 0; i < 2; i++)
        #pragma unroll
        for (int j = 0; j < 4; j++)
            #pragma unroll
            for (int k = 0; k < 4; k++) d[i][j][k] = 0.0f;

    float4 areg[2];
    ldgA(Arows, 0, tid, areg);
    stsA(sbase, tid, areg);
    ldB(Bh, Bl, 0, sbase, tid); CP_COMMIT();
    ldgA(Arows, 1, tid, areg);
    ldB(Bh, Bl, 1, sbase + STAGE_B, tid); CP_COMMIT();

    uint32_t aoff[2], boff[2];
    #pragma unroll
    for (int s = 0; s < 2; s++) {
        int arow = wm * 32 + (lane & 15);
        int acol = s * 32 + (lane >> 4) * 16;
        aoff[s] = swz(arow * 64 + acol);
        int brow = wn * 32 + ((lane >> 4) & 1) * 8 + (lane & 7);
        int bcol = s * 32 + ((lane >> 3) & 1) * 16;
        boff[s] = swz(brow * 64 + bcol);
    }

    for (int kt = 0; kt < ktn; kt++) {
        CP_WAIT1();
        __syncthreads();
        if (kt + 1 < ktn)
            stsA(sbase + ((kt + 1) % NST) * STAGE_B, tid, areg);
        if (kt + 2 < ktn) {
            ldgA(Arows, kt + 2, tid, areg);
            ldB(Bh, Bl, kt + 2, sbase + ((kt + 2) % NST) * STAGE_B, tid);
        }
        CP_COMMIT();

        uint32_t sAh = sbase + (kt % NST) * STAGE_B;
        uint32_t sAl = sAh + 4096;
        uint32_t sBh = sAh + 8192;
        uint32_t sBl = sAh + 16384;
        #pragma unroll
        for (int s = 0; s < 2; s++) {
            uint32_t a[2][4], bh[4][2], bl[4][2];
            #pragma unroll
            for (int f = 0; f < 2; f++)
                ldm4(sAh + f * 1024 + aoff[s], a[f][0], a[f][1], a[f][2], a[f][3]);
            #pragma unroll
            for (int p = 0; p < 2; p++)
                ldm4(sBh + p * 1024 + boff[s],
                     bh[2 * p][0], bh[2 * p][1], bh[2 * p + 1][0], bh[2 * p + 1][1]);
            #pragma unroll
            for (int mf = 0; mf < 2; mf++)
                #pragma unroll
                for (int nf = 0; nf < 4; nf++)
                    mma16816(d[mf][nf], a[mf], bh[nf]);
            #pragma unroll
            for (int p = 0; p < 2; p++)
                ldm4(sBl + p * 1024 + boff[s],
                     bl[2 * p][0], bl[2 * p][1], bl[2 * p + 1][0], bl[2 * p + 1][1]);
            #pragma unroll
            for (int mf = 0; mf < 2; mf++)
                #pragma unroll
                for (int nf = 0; nf < 4; nf++)
                    mma16816(d[mf][nf], a[mf], bl[nf]);
            #pragma unroll
            for (int f = 0; f < 2; f++)
                ldm4(sAl + f * 1024 + aoff[s], a[f][0], a[f][1], a[f][2], a[f][3]);
            #pragma unroll
            for (int mf = 0; mf < 2; mf++)
                #pragma unroll
                for (int nf = 0; nf < 4; nf++)
                    mma16816(d[mf][nf], a[mf], bh[nf]);
        }
    }
    CP_WAIT0();

    // epilogue: add per-segment mean addend (g_M includes both biases)
    #pragma unroll
    for (int mf = 0; mf < 2; mf++) {
        int r0 = m0 + wm * 32 + mf * 16 + (lane >> 2);
        int s0 = g_seg[r0], s1 = g_seg[r0 + 8];
        #pragma unroll
        for (int nf = 0; nf < 4; nf++) {
            int c = n0 + wn * 32 + nf * 8 + (lane & 3) * 2;
            float2 M0 = *(const float2*)(g_M + (size_t)s0 * P_ + c);
            float2 M1 = *(const float2*)(g_M + (size_t)s1 * P_ + c);
            *(float2*)(out + (size_t)r0 * P_ + c)
                = make_float2(d[mf][nf][0] + M0.x, d[mf][nf][1] + M0.y);
            *(float2*)(out + (size_t)(r0 + 8) * P_ + c)
                = make_float2(d[mf][nf][2] + M1.x, d[mf][nf][3] + M1.y);
        }
    }
}

// =============== mean GEMM: g_mpart[ks] = segsum_x @ W2^T (1-term bf16) ======
// CTA 64x128, BK=32 bf16, K-split 4 (512 each, 16 tiles).
#define MSTAGE_B 12288
#define MSMEM_REQ (NST * MSTAGE_B)

__device__ __forceinline__ void stsA1(uint32_t sg, int tid, const float4* areg) {
    int row = tid >> 2, h = tid & 3;
    uint32_t h0, h1, h2, h3;
    packh4(areg[0], h0, h1);
    packh4(areg[1], h2, h3);
    sts16(sg + swz(row * 64 + h * 16), h0, h1, h2, h3);
}
__device__ __forceinline__ void ldB1(const char* Bh, int kt, uint32_t sg, int tid) {
    int k0 = kt << 6;   // bytes
    #pragma unroll
    for (int i = 0; i < 2; i++) {
        int idx = i * 256 + tid;
        int row = idx >> 2, c = idx & 3;
        uint32_t off = swz(row * 64 + c * 16);
        cp16(sg + 4096 + off, Bh + (size_t)row * (D_ * 2) + k0 + c * 16);
    }
}

__global__ void __launch_bounds__(256, 3) k_mgemm() {
    extern __shared__ __align__(128) char smem[];
    uint32_t sbase = smem_u32(smem);
    int tid = threadIdx.x, lane = tid & 31, wid = tid >> 5;
    int wm = wid & 1, wn = wid >> 1;
    int n0 = blockIdx.x * 128, m0 = blockIdx.y * 64, ks = blockIdx.z;
    const float* Arows = g_sumx + (size_t)m0 * D_ + ks * 512;
    const char*  Bh    = (const char*)(g_bhi + (size_t)(256 + n0) * D_ + ks * 512);
    float* dst = g_mpart + (size_t)ks * NSEG * P_ + (size_t)m0 * P_ + n0;
    const int ktn = 16;

    float d[2][4][4];
    #pragma unroll
    for (int i = 0; i < 2; i++)
        #pragma unroll
        for (int j = 0; j < 4; j++)
            #pragma unroll
            for (int k = 0; k < 4; k++) d[i][j][k] = 0.0f;

    float4 areg[2];
    ldgA(Arows, 0, tid, areg);
    stsA1(sbase, tid, areg);
    ldB1(Bh, 0, sbase, tid); CP_COMMIT();
    ldgA(Arows, 1, tid, areg);
    ldB1(Bh, 1, sbase + MSTAGE_B, tid); CP_COMMIT();

    uint32_t aoff[2], boff[2];
    #pragma unroll
    for (int s = 0; s < 2; s++) {
        int arow = wm * 32 + (lane & 15);
        int acol = s * 32 + (lane >> 4) * 16;
        aoff[s] = swz(arow * 64 + acol);
        int brow = wn * 32 + ((lane >> 4) & 1) * 8 + (lane & 7);
        int bcol = s * 32 + ((lane >> 3) & 1) * 16;
        boff[s] = swz(brow * 64 + bcol);
    }

    for (int kt = 0; kt < ktn; kt++) {
        CP_WAIT1();
        __syncthreads();
        if (kt + 1 < ktn)
            stsA1(sbase + ((kt + 1) % NST) * MSTAGE_B, tid, areg);
        if (kt + 2 < ktn) {
            ldgA(Arows, kt + 2, tid, areg);
            ldB1(Bh, kt + 2, sbase + ((kt + 2) % NST) * MSTAGE_B, tid);
        }
        CP_COMMIT();

        uint32_t sA = sbase + (kt % NST) * MSTAGE_B;
        uint32_t sB = sA + 4096;
        #pragma unroll
        for (int s = 0; s < 2; s++) {
            uint32_t a[2][4], b[4][2];
            #pragma unroll
            for (int f = 0; f < 2; f++)
                ldm4(sA + f * 1024 + aoff[s], a[f][0], a[f][1], a[f][2], a[f][3]);
            #pragma unroll
            for (int p = 0; p < 2; p++)
                ldm4(sB + p * 1024 + boff[s],
                     b[2 * p][0], b[2 * p][1], b[2 * p + 1][0], b[2 * p + 1][1]);
            #pragma unroll
            for (int mf = 0; mf < 2; mf++)
                #pragma unroll
                for (int nf = 0; nf < 4; nf++)
                    mma16816(d[mf][nf], a[mf], b[nf]);
        }
    }
    CP_WAIT0();

    #pragma unroll
    for (int mf = 0; mf < 2; mf++) {
        #pragma unroll
        for (int nf = 0; nf < 4; nf++) {
            int r = wm * 32 + mf * 16 + (lane >> 2);
            int c = wn * 32 + nf * 8 + (lane & 3) * 2;
            *(float2*)(dst + (size_t)r * P_ + c)
                = make_float2(d[mf][nf][0], d[mf][nf][1]);
            *(float2*)(dst + (size_t)(r + 8) * P_ + c)
                = make_float2(d[mf][nf][2], d[mf][nf][3]);
        }
    }
}

// ---------------- reduce K-split parts ---------------------------------------
__global__ void k_mred() {
    int i = blockIdx.x * blockDim.x + threadIdx.x;
    float s = g_mpart[i] + g_mpart[NSEG * P_ + i]
            + g_mpart[2 * NSEG * P_ + i] + g_mpart[3 * NSEG * P_ + i];
    g_sum_bl2[i] = s;
}

// ---------------- per-batch sums from per-seg sums ---------------------------
__global__ void k_sumb() {
    int b = blockIdx.x, h = blockIdx.y;
    int col = h * 128 + threadIdx.x;
    const float* base = g_sum_bl2 + (size_t)(b * NL) * P_ + col;
    float acc = 0.0f;
    #pragma unroll 4
    for (int l = 0; l < NL; l++) acc += base[(size_t)l * P_];
    g_sum_b2[b * P_ + col] = acc;
}

// ---------------- per-segment output addend ----------------------------------
__global__ void k_minv() {
    int s = blockIdx.x, t = threadIdx.x;
    int b = s / NL;
    int cb = g_bstart[b + 1] - g_bstart[b];
    int d = cb - g_cnt[s];
    float inv = (d > 0) ? (1.0f / (float)d) : 0.0f;
    float m = (g_sum_b2[b * P_ + t] - g_sum_bl2[(size_t)s * P_ + t]) * inv;
    g_M[(size_t)s * P_ + t] = m + g_bias[t];
}

// ---------------- launch -----------------------------------------------------
extern "C" void kernel_launch(void* const* d_in, const int* in_sizes, int n_in,
                              void* d_out, int out_size) {
    const float* x     = (const float*)d_in[0];
    const int*   label = (const int*)  d_in[1];
    const int*   lb    = (const int*)  d_in[2];
    const float* W1_w  = (const float*)d_in[3];
    const float* W1_b  = (const float*)d_in[4];
    const float* W2_w  = (const float*)d_in[5];
    const float* W2_b  = (const float*)d_in[6];
    float* out = (float*)d_out;

    cudaFuncSetAttribute(k_gemm,   cudaFuncAttributeMaxDynamicSharedMemorySize, SMEM_REQ);
    cudaFuncSetAttribute(k_mgemm,  cudaFuncAttributeMaxDynamicSharedMemorySize, MSMEM_REQ);
    cudaFuncSetAttribute(k_segsum, cudaFuncAttributeMaxDynamicSharedMemorySize, SEG_SMEM);

    k_convw<<<(512 * D_ / 4) / 256, 256>>>(W1_w, W2_w, W1_b, W2_b);
    k_detect<<<1, 256>>>(label, lb);
    k_prep<<<N_ / 256, 256>>>(label, lb);
    k_segsum<<<dim3(D_ / 64, NB), 256, SEG_SMEM>>>(x);
    k_mgemm<<<dim3(2, NSEG / 64, 4), 256, MSMEM_REQ>>>();
    k_mred<<<(NSEG * P_) / 256, 256>>>();
    k_sumb<<<dim3(NB, 2), 128>>>();
    k_minv<<<NSEG, 256>>>();
    k_gemm<<<dim3(2, 256), 256, SMEM_REQ>>>(x, out);
}

// round 10
// speedup vs baseline: 3.3840x; 1.1963x over previous
#include <cuda_runtime.h>
#include <cuda_bf16.h>
#include <cstdint>

#define N_   16384
#define D_   2048
#define P_   256
#define NB   32
#define NL   100
#define NSEG (NB*NL)
#define NST  3          // pipeline stages

// ---------------- scratch globals (no allocations allowed) -------------------
__device__ __nv_bfloat16 g_bhi[512 * D_];   // [W1;W2] hi
__device__ __nv_bfloat16 g_blo[512 * D_];   // [W1;W2] lo (W2 half unused)
__device__ float g_sumx[NSEG * D_];         // exact fp32 segsum of x
__device__ float g_mpart[4 * NSEG * P_];    // K-split partials of segsum@W2^T
__device__ float g_sum_bl2[NSEG * P_];
__device__ float g_sum_b2 [NB   * P_];
__device__ float g_M[NSEG * P_];
__device__ float g_bias[P_];
__device__ int   g_cnt[NSEG];
__device__ int   g_off[NSEG + 1];
__device__ int   g_cur[NSEG];
__device__ int   g_rows[N_];
__device__ int   g_seg[N_];
__device__ int   g_bstart[NB + 1];
__device__ int   g_is64;

// ---------------- PTX helpers ------------------------------------------------
__device__ __forceinline__ uint32_t smem_u32(const void* p) {
    uint32_t a;
    asm("{ .reg .u64 t; cvta.to.shared.u64 t, %1; cvt.u32.u64 %0, t; }" : "=r"(a) : "l"(p));
    return a;
}
__device__ __forceinline__ void cp16(uint32_t dst, const void* src) {
    asm volatile("cp.async.cg.shared.global [%0], [%1], 16;" :: "r"(dst), "l"(src));
}
#define CP_COMMIT() asm volatile("cp.async.commit_group;" ::: "memory")
#define CP_WAIT1()  asm volatile("cp.async.wait_group 1;"  ::: "memory")
#define CP_WAIT0()  asm volatile("cp.async.wait_group 0;"  ::: "memory")

__device__ __forceinline__ uint32_t swz(uint32_t o) {   // 64B-row swizzle
    return o ^ ((o >> 3) & 0x30);
}
__device__ __forceinline__ void ldm4(uint32_t addr, uint32_t& r0, uint32_t& r1,
                                     uint32_t& r2, uint32_t& r3) {
    asm volatile("ldmatrix.sync.aligned.m8n8.x4.shared.b16 {%0,%1,%2,%3}, [%4];"
                 : "=r"(r0), "=r"(r1), "=r"(r2), "=r"(r3) : "r"(addr));
}
__device__ __forceinline__ void mma16816(float* d, const uint32_t* a,
                                         const uint32_t* b) {
    asm volatile(
        "mma.sync.aligned.m16n8k16.row.col.f32.bf16.bf16.f32 "
        "{%0,%1,%2,%3}, {%4,%5,%6,%7}, {%8,%9}, {%0,%1,%2,%3};"
        : "+f"(d[0]), "+f"(d[1]), "+f"(d[2]), "+f"(d[3])
        : "r"(a[0]), "r"(a[1]), "r"(a[2]), "r"(a[3]), "r"(b[0]), "r"(b[1]));
}
__device__ __forceinline__ void sts16(uint32_t addr, uint32_t r0, uint32_t r1,
                                      uint32_t r2, uint32_t r3) {
    asm volatile("st.shared.v4.b32 [%0], {%1,%2,%3,%4};"
                 :: "r"(addr), "r"(r0), "r"(r1), "r"(r2), "r"(r3) : "memory");
}

// 4 floats -> hi bf16x2 pair + lo bf16x2 pair
__device__ __forceinline__ void pack_hilo(float4 v, uint32_t& h0, uint32_t& h1,
                                          uint32_t& l0, uint32_t& l1) {
    __nv_bfloat16 a = __float2bfloat16(v.x), b = __float2bfloat16(v.y);
    __nv_bfloat16 c = __float2bfloat16(v.z), d = __float2bfloat16(v.w);
    __nv_bfloat16 e = __float2bfloat16(v.x - __bfloat162float(a));
    __nv_bfloat16 f = __float2bfloat16(v.y - __bfloat162float(b));
    __nv_bfloat16 g = __float2bfloat16(v.z - __bfloat162float(c));
    __nv_bfloat16 h = __float2bfloat16(v.w - __bfloat162float(d));
    __nv_bfloat162 hh0(a, b), hh1(c, d), ll0(e, f), ll1(g, h);
    h0 = *(uint32_t*)&hh0; h1 = *(uint32_t*)&hh1;
    l0 = *(uint32_t*)&ll0; l1 = *(uint32_t*)&ll1;
}
__device__ __forceinline__ void packh4(float4 v, uint32_t& h0, uint32_t& h1) {
    __nv_bfloat162 p0(__float2bfloat16(v.x), __float2bfloat16(v.y));
    __nv_bfloat162 p1(__float2bfloat16(v.z), __float2bfloat16(v.w));
    h0 = *(uint32_t*)&p0; h1 = *(uint32_t*)&p1;
}

// ---------------- dtype detection + count zeroing ----------------------------
__global__ void k_detect(const int* label, const int* lb) {
    __shared__ int nz_la, nz_lb;
    int t = threadIdx.x;
    if (t == 0) { nz_la = 0; nz_lb = 0; }
    __syncthreads();
    if (t < 64) {
        int w = 2 * (t * 128) + 1;
        if (label[w] != 0) atomicOr(&nz_la, 1);
        if (lb[w]    != 0) atomicOr(&nz_lb, 1);
    }
    __syncthreads();
    if (t == 0) g_is64 = (nz_la ? 0 : 1) | (nz_lb ? 0 : 2);
    for (int i = t; i < NSEG; i += blockDim.x) g_cnt[i] = 0;
}
__device__ __forceinline__ int ld_idx(const int* p, int i, bool is64) {
    return is64 ? p[2 * i] : p[i];
}

// ---------------- seg ids, counts, batch boundaries --------------------------
__global__ void k_prep(const int* label, const int* lb) {
    bool la64 = (g_is64 & 1) != 0, lb64 = (g_is64 & 2) != 0;
    int i = blockIdx.x * blockDim.x + threadIdx.x;
    if (i < N_) {
        int la = ld_idx(label, i, la64);
        int b  = ld_idx(lb,    i, lb64);
        int s  = b * NL + la;
        g_seg[i] = s;
        atomicAdd(&g_cnt[s], 1);
    }
    if (blockIdx.x == 0 && threadIdx.x <= NB) {
        int target = threadIdx.x;
        int lo = 0, hi = N_;
        while (lo < hi) {
            int mid = (lo + hi) >> 1;
            if (ld_idx(lb, mid, lb64) < target) lo = mid + 1; else hi = mid;
        }
        g_bstart[target] = lo;
    }
}

// ---------------- prefix scan over seg counts --------------------------------
__global__ void k_scan() {
    __shared__ int sh[1024];
    int t = threadIdx.x;
    int base = t * 4;
    int c[4];
    #pragma unroll
    for (int i = 0; i < 4; i++) c[i] = (base + i < NSEG) ? g_cnt[base + i] : 0;
    int tot = c[0] + c[1] + c[2] + c[3];
    sh[t] = tot;
    __syncthreads();
    int run = tot;
    for (int d = 1; d < 1024; d <<= 1) {
        int v = (t >= d) ? sh[t - d] : 0;
        __syncthreads();
        run += v; sh[t] = run;
        __syncthreads();
    }
    int excl = (t > 0) ? sh[t - 1] : 0;
    int p = excl;
    #pragma unroll
    for (int i = 0; i < 4; i++) {
        if (base + i <= NSEG) g_off[base + i] = p;
        if (base + i <  NSEG) g_cur[base + i] = p;
        p += c[i];
    }
}

// ---------------- scatter rows by segment ------------------------------------
__global__ void k_scatter() {
    int i = blockIdx.x * blockDim.x + threadIdx.x;
    int s = g_seg[i];
    int pos = atomicAdd(&g_cur[s], 1);
    g_rows[pos] = i;
}

// ---------------- weight hi/lo conversion ------------------------------------
__global__ void k_convw(const float* __restrict__ W1, const float* __restrict__ W2,
                        const float* __restrict__ b1, const float* __restrict__ b2) {
    int i = blockIdx.x * blockDim.x + threadIdx.x;   // float4 index over 512x2048
    int e = i * 4;
    int row = e >> 11;
    int col = e & 2047;
    const float* src = (row < 256) ? (W1 + (size_t)row * D_ + col)
                                   : (W2 + (size_t)(row - 256) * D_ + col);
    float4 v = *(const float4*)src;
    uint32_t h0, h1, l0, l1;
    pack_hilo(v, h0, h1, l0, l1);
    ((uint2*)g_bhi)[i] = make_uint2(h0, h1);
    ((uint2*)g_blo)[i] = make_uint2(l0, l1);
    if (blockIdx.x == 0 && threadIdx.x < P_)
        g_bias[threadIdx.x] = b1[threadIdx.x] + b2[threadIdx.x];
}

// ---------------- segment sums: sorted gather, register accumulation ----------
// grid (D/64, NSEG/16), block 256 = 64 cols x 4 seg-lanes; each thread owns
// one (segment, col) pair per j-iter, accumulates in registers. No smem.
__global__ void k_segsum(const float* __restrict__ x) {
    int c0  = blockIdx.x * 64;
    int gseg = blockIdx.y * 16;
    int t = threadIdx.x;
    int col = t & 63, sl = t >> 6;
    #pragma unroll
    for (int j = 0; j < 4; j++) {
        int s = gseg + sl * 4 + j;
        int i0 = g_off[s], i1 = g_off[s + 1];
        float acc0 = 0.0f, acc1 = 0.0f;
        int i = i0;
        for (; i + 2 <= i1; i += 2) {
            int r0 = g_rows[i], r1 = g_rows[i + 1];
            acc0 += x[(size_t)r0 * D_ + c0 + col];
            acc1 += x[(size_t)r1 * D_ + c0 + col];
        }
        if (i < i1) acc0 += x[(size_t)g_rows[i] * D_ + c0 + col];
        g_sumx[(size_t)s * D_ + c0 + col] = acc0 + acc1;
    }
}

// =============== main GEMM: out = x @ W1^T (3-term bf16) + M[seg] ============
// CTA tile 64(M) x 128(N), BK=32, 256 threads, warp grid 2x4 (tile 32x32).
// Stage: A_hi 4K | A_lo 4K | B_hi 8K | B_lo 8K = 24KB.  NST=3 -> 72KB.
#define STAGE_B 24576
#define SMEM_REQ (NST * STAGE_B)

__device__ __forceinline__ void ldgA(const float* __restrict__ Arows, int kt,
                                     int tid, float4* areg) {
    int row = tid >> 2, h = tid & 3;                 // 4 thr/row, 8 floats each
    const float4* p = (const float4*)(Arows + (size_t)row * D_ + (kt << 5) + h * 8);
    areg[0] = p[0]; areg[1] = p[1];
}
__device__ __forceinline__ void stsA(uint32_t sg, int tid, const float4* areg) {
    int row = tid >> 2, h = tid & 3;
    uint32_t h0a, h1a, l0a, l1a, h0b, h1b, l0b, l1b;
    pack_hilo(areg[0], h0a, h1a, l0a, l1a);
    pack_hilo(areg[1], h0b, h1b, l0b, l1b);
    uint32_t o = swz(row * 64 + h * 16);
    sts16(sg + o,        h0a, h1a, h0b, h1b);        // A_hi
    sts16(sg + 4096 + o, l0a, l1a, l0b, l1b);        // A_lo
}
__device__ __forceinline__ void ldB(const __nv_bfloat16* Bh, const __nv_bfloat16* Bl,
                                    int kt, uint32_t sg, int tid) {
    int k0 = kt << 5;
    const char* gBh = (const char*)(Bh + k0);
    const char* gBl = (const char*)(Bl + k0);
    #pragma unroll
    for (int i = 0; i < 2; i++) {
        int idx = i * 256 + tid;
        int row = idx >> 2, c = idx & 3;
        uint32_t off = swz(row * 64 + c * 16);
        cp16(sg + 8192  + off, gBh + (size_t)row * (D_ * 2) + c * 16);
        cp16(sg + 16384 + off, gBl + (size_t)row * (D_ * 2) + c * 16);
    }
}

__global__ void __launch_bounds__(256, 3) k_gemm(const float* __restrict__ x,
                                                 float* __restrict__ out) {
    extern __shared__ __align__(128) char smem[];
    uint32_t sbase = smem_u32(smem);
    int tid = threadIdx.x, lane = tid & 31, wid = tid >> 5;
    int wm = wid & 1, wn = wid >> 1;                 // warp grid 2(M) x 4(N)
    int n0 = blockIdx.x * 128, m0 = blockIdx.y * 64;
    const float* Arows = x + (size_t)m0 * D_;
    const __nv_bfloat16* Bh = g_bhi + (size_t)n0 * D_;
    const __nv_bfloat16* Bl = g_blo + (size_t)n0 * D_;
    const int ktn = 64;

    float d[2][4][4];
    #pragma unroll
    for (int i = 0; i < 2; i++)
        #pragma unroll
        for (int j = 0; j < 4; j++)
            #pragma unroll
            for (int k = 0; k < 4; k++) d[i][j][k] = 0.0f;

    float4 areg[2];
    ldgA(Arows, 0, tid, areg);
    stsA(sbase, tid, areg);
    ldB(Bh, Bl, 0, sbase, tid); CP_COMMIT();
    ldgA(Arows, 1, tid, areg);
    ldB(Bh, Bl, 1, sbase + STAGE_B, tid); CP_COMMIT();

    uint32_t aoff[2], boff[2];
    #pragma unroll
    for (int s = 0; s < 2; s++) {
        int arow = wm * 32 + (lane & 15);
        int acol = s * 32 + (lane >> 4) * 16;
        aoff[s] = swz(arow * 64 + acol);
        int brow = wn * 32 + ((lane >> 4) & 1) * 8 + (lane & 7);
        int bcol = s * 32 + ((lane >> 3) & 1) * 16;
        boff[s] = swz(brow * 64 + bcol);
    }

    for (int kt = 0; kt < ktn; kt++) {
        CP_WAIT1();
        __syncthreads();
        if (kt + 1 < ktn)
            stsA(sbase + ((kt + 1) % NST) * STAGE_B, tid, areg);
        if (kt + 2 < ktn) {
            ldgA(Arows, kt + 2, tid, areg);
            ldB(Bh, Bl, kt + 2, sbase + ((kt + 2) % NST) * STAGE_B, tid);
        }
        CP_COMMIT();

        uint32_t sAh = sbase + (kt % NST) * STAGE_B;
        uint32_t sAl = sAh + 4096;
        uint32_t sBh = sAh + 8192;
        uint32_t sBl = sAh + 16384;
        #pragma unroll
        for (int s = 0; s < 2; s++) {
            uint32_t a[2][4], bh[4][2], bl[4][2];
            #pragma unroll
            for (int f = 0; f < 2; f++)
                ldm4(sAh + f * 1024 + aoff[s], a[f][0], a[f][1], a[f][2], a[f][3]);
            #pragma unroll
            for (int p = 0; p < 2; p++)
                ldm4(sBh + p * 1024 + boff[s],
                     bh[2 * p][0], bh[2 * p][1], bh[2 * p + 1][0], bh[2 * p + 1][1]);
            #pragma unroll
            for (int mf = 0; mf < 2; mf++)
                #pragma unroll
                for (int nf = 0; nf < 4; nf++)
                    mma16816(d[mf][nf], a[mf], bh[nf]);
            #pragma unroll
            for (int p = 0; p < 2; p++)
                ldm4(sBl + p * 1024 + boff[s],
                     bl[2 * p][0], bl[2 * p][1], bl[2 * p + 1][0], bl[2 * p + 1][1]);
            #pragma unroll
            for (int mf = 0; mf < 2; mf++)
                #pragma unroll
                for (int nf = 0; nf < 4; nf++)
                    mma16816(d[mf][nf], a[mf], bl[nf]);
            #pragma unroll
            for (int f = 0; f < 2; f++)
                ldm4(sAl + f * 1024 + aoff[s], a[f][0], a[f][1], a[f][2], a[f][3]);
            #pragma unroll
            for (int mf = 0; mf < 2; mf++)
                #pragma unroll
                for (int nf = 0; nf < 4; nf++)
                    mma16816(d[mf][nf], a[mf], bh[nf]);
        }
    }
    CP_WAIT0();

    // epilogue: add per-segment mean addend (g_M includes both biases)
    #pragma unroll
    for (int mf = 0; mf < 2; mf++) {
        int r0 = m0 + wm * 32 + mf * 16 + (lane >> 2);
        int s0 = g_seg[r0], s1 = g_seg[r0 + 8];
        #pragma unroll
        for (int nf = 0; nf < 4; nf++) {
            int c = n0 + wn * 32 + nf * 8 + (lane & 3) * 2;
            float2 M0 = *(const float2*)(g_M + (size_t)s0 * P_ + c);
            float2 M1 = *(const float2*)(g_M + (size_t)s1 * P_ + c);
            *(float2*)(out + (size_t)r0 * P_ + c)
                = make_float2(d[mf][nf][0] + M0.x, d[mf][nf][1] + M0.y);
            *(float2*)(out + (size_t)(r0 + 8) * P_ + c)
                = make_float2(d[mf][nf][2] + M1.x, d[mf][nf][3] + M1.y);
        }
    }
}

// =============== mean GEMM: g_mpart[ks] = segsum_x @ W2^T (1-term bf16) ======
// CTA 64x128, BK=32 bf16, K-split 4 (512 each, 16 tiles).
#define MSTAGE_B 12288
#define MSMEM_REQ (NST * MSTAGE_B)

__device__ __forceinline__ void stsA1(uint32_t sg, int tid, const float4* areg) {
    int row = tid >> 2, h = tid & 3;
    uint32_t h0, h1, h2, h3;
    packh4(areg[0], h0, h1);
    packh4(areg[1], h2, h3);
    sts16(sg + swz(row * 64 + h * 16), h0, h1, h2, h3);
}
__device__ __forceinline__ void ldB1(const char* Bh, int kt, uint32_t sg, int tid) {
    int k0 = kt << 6;   // bytes
    #pragma unroll
    for (int i = 0; i < 2; i++) {
        int idx = i * 256 + tid;
        int row = idx >> 2, c = idx & 3;
        uint32_t off = swz(row * 64 + c * 16);
        cp16(sg + 4096 + off, Bh + (size_t)row * (D_ * 2) + k0 + c * 16);
    }
}

__global__ void __launch_bounds__(256, 3) k_mgemm() {
    extern __shared__ __align__(128) char smem[];
    uint32_t sbase = smem_u32(smem);
    int tid = threadIdx.x, lane = tid & 31, wid = tid >> 5;
    int wm = wid & 1, wn = wid >> 1;
    int n0 = blockIdx.x * 128, m0 = blockIdx.y * 64, ks = blockIdx.z;
    const float* Arows = g_sumx + (size_t)m0 * D_ + ks * 512;
    const char*  Bh    = (const char*)(g_bhi + (size_t)(256 + n0) * D_ + ks * 512);
    float* dst = g_mpart + (size_t)ks * NSEG * P_ + (size_t)m0 * P_ + n0;
    const int ktn = 16;

    float d[2][4][4];
    #pragma unroll
    for (int i = 0; i < 2; i++)
        #pragma unroll
        for (int j = 0; j < 4; j++)
            #pragma unroll
            for (int k = 0; k < 4; k++) d[i][j][k] = 0.0f;

    float4 areg[2];
    ldgA(Arows, 0, tid, areg);
    stsA1(sbase, tid, areg);
    ldB1(Bh, 0, sbase, tid); CP_COMMIT();
    ldgA(Arows, 1, tid, areg);
    ldB1(Bh, 1, sbase + MSTAGE_B, tid); CP_COMMIT();

    uint32_t aoff[2], boff[2];
    #pragma unroll
    for (int s = 0; s < 2; s++) {
        int arow = wm * 32 + (lane & 15);
        int acol = s * 32 + (lane >> 4) * 16;
        aoff[s] = swz(arow * 64 + acol);
        int brow = wn * 32 + ((lane >> 4) & 1) * 8 + (lane & 7);
        int bcol = s * 32 + ((lane >> 3) & 1) * 16;
        boff[s] = swz(brow * 64 + bcol);
    }

    for (int kt = 0; kt < ktn; kt++) {
        CP_WAIT1();
        __syncthreads();
        if (kt + 1 < ktn)
            stsA1(sbase + ((kt + 1) % NST) * MSTAGE_B, tid, areg);
        if (kt + 2 < ktn) {
            ldgA(Arows, kt + 2, tid, areg);
            ldB1(Bh, kt + 2, sbase + ((kt + 2) % NST) * MSTAGE_B, tid);
        }
        CP_COMMIT();

        uint32_t sA = sbase + (kt % NST) * MSTAGE_B;
        uint32_t sB = sA + 4096;
        #pragma unroll
        for (int s = 0; s < 2; s++) {
            uint32_t a[2][4], b[4][2];
            #pragma unroll
            for (int f = 0; f < 2; f++)
                ldm4(sA + f * 1024 + aoff[s], a[f][0], a[f][1], a[f][2], a[f][3]);
            #pragma unroll
            for (int p = 0; p < 2; p++)
                ldm4(sB + p * 1024 + boff[s],
                     b[2 * p][0], b[2 * p][1], b[2 * p + 1][0], b[2 * p + 1][1]);
            #pragma unroll
            for (int mf = 0; mf < 2; mf++)
                #pragma unroll
                for (int nf = 0; nf < 4; nf++)
                    mma16816(d[mf][nf], a[mf], b[nf]);
        }
    }
    CP_WAIT0();

    #pragma unroll
    for (int mf = 0; mf < 2; mf++) {
        #pragma unroll
        for (int nf = 0; nf < 4; nf++) {
            int r = wm * 32 + mf * 16 + (lane >> 2);
            int c = wn * 32 + nf * 8 + (lane & 3) * 2;
            *(float2*)(dst + (size_t)r * P_ + c)
                = make_float2(d[mf][nf][0], d[mf][nf][1]);
            *(float2*)(dst + (size_t)(r + 8) * P_ + c)
                = make_float2(d[mf][nf][2], d[mf][nf][3]);
        }
    }
}

// ---------------- reduce K-split parts ---------------------------------------
__global__ void k_mred() {
    int i = blockIdx.x * blockDim.x + threadIdx.x;
    float s = g_mpart[i] + g_mpart[NSEG * P_ + i]
            + g_mpart[2 * NSEG * P_ + i] + g_mpart[3 * NSEG * P_ + i];
    g_sum_bl2[i] = s;
}

// ---------------- per-batch sums from per-seg sums ---------------------------
__global__ void k_sumb() {
    int b = blockIdx.x, h = blockIdx.y;
    int col = h * 128 + threadIdx.x;
    const float* base = g_sum_bl2 + (size_t)(b * NL) * P_ + col;
    float acc = 0.0f;
    #pragma unroll 4
    for (int l = 0; l < NL; l++) acc += base[(size_t)l * P_];
    g_sum_b2[b * P_ + col] = acc;
}

// ---------------- per-segment output addend ----------------------------------
__global__ void k_minv() {
    int s = blockIdx.x, t = threadIdx.x;
    int b = s / NL;
    int cb = g_bstart[b + 1] - g_bstart[b];
    int d = cb - g_cnt[s];
    float inv = (d > 0) ? (1.0f / (float)d) : 0.0f;
    float m = (g_sum_b2[b * P_ + t] - g_sum_bl2[(size_t)s * P_ + t]) * inv;
    g_M[(size_t)s * P_ + t] = m + g_bias[t];
}

// ---------------- launch -----------------------------------------------------
extern "C" void kernel_launch(void* const* d_in, const int* in_sizes, int n_in,
                              void* d_out, int out_size) {
    const float* x     = (const float*)d_in[0];
    const int*   label = (const int*)  d_in[1];
    const int*   lb    = (const int*)  d_in[2];
    const float* W1_w  = (const float*)d_in[3];
    const float* W1_b  = (const float*)d_in[4];
    const float* W2_w  = (const float*)d_in[5];
    const float* W2_b  = (const float*)d_in[6];
    float* out = (float*)d_out;

    cudaFuncSetAttribute(k_gemm,  cudaFuncAttributeMaxDynamicSharedMemorySize, SMEM_REQ);
    cudaFuncSetAttribute(k_mgemm, cudaFuncAttributeMaxDynamicSharedMemorySize, MSMEM_REQ);

    k_convw<<<(512 * D_ / 4) / 256, 256>>>(W1_w, W2_w, W1_b, W2_b);
    k_detect<<<1, 256>>>(label, lb);
    k_prep<<<N_ / 256, 256>>>(label, lb);
    k_scan<<<1, 1024>>>();
    k_scatter<<<N_ / 256, 256>>>();
    k_segsum<<<dim3(D_ / 64, NSEG / 16), 256>>>(x);
    k_mgemm<<<dim3(2, NSEG / 64, 4), 256, MSMEM_REQ>>>();
    k_mred<<<(NSEG * P_) / 256, 256>>>();
    k_sumb<<<dim3(NB, 2), 128>>>();
    k_minv<<<NSEG, 256>>>();
    k_gemm<<<dim3(2, 256), 256, SMEM_REQ>>>(x, out);
}

// round 11
// speedup vs baseline: 3.5305x; 1.0433x over previous
#include <cuda_runtime.h>
#include <cuda_bf16.h>
#include <cstdint>

#define N_   16384
#define D_   2048
#define P_   256
#define NB   32
#define NL   100
#define NSEG (NB*NL)
#define NST  3          // pipeline stages

// ---------------- scratch globals (no allocations allowed) -------------------
__device__ __nv_bfloat16 g_bhi[512 * D_];   // [W1;W2] hi
__device__ __nv_bfloat16 g_blo[512 * D_];   // [W1;W2] lo (W2 half unused)
__device__ float g_sumx[NSEG * D_];         // exact fp32 segsum of x
__device__ float g_mpart[4 * NSEG * P_];    // K-split partials of segsum@W2^T
__device__ float g_sum_bl2[NSEG * P_];
__device__ float g_sum_b2 [NB   * P_];
__device__ float g_M[NSEG * P_];
__device__ float g_bias[P_];
__device__ int   g_cnt[NSEG];
__device__ int   g_off[NSEG + 1];
__device__ int   g_cur[NSEG];
__device__ int   g_rows[N_];
__device__ int   g_seg[N_];
__device__ int   g_bstart[NB + 1];
__device__ int   g_is64;

// ---------------- PTX helpers ------------------------------------------------
__device__ __forceinline__ uint32_t smem_u32(const void* p) {
    uint32_t a;
    asm("{ .reg .u64 t; cvta.to.shared.u64 t, %1; cvt.u32.u64 %0, t; }" : "=r"(a) : "l"(p));
    return a;
}
__device__ __forceinline__ void cp16(uint32_t dst, const void* src) {
    asm volatile("cp.async.cg.shared.global [%0], [%1], 16;" :: "r"(dst), "l"(src));
}
#define CP_COMMIT() asm volatile("cp.async.commit_group;" ::: "memory")
#define CP_WAIT1()  asm volatile("cp.async.wait_group 1;"  ::: "memory")
#define CP_WAIT0()  asm volatile("cp.async.wait_group 0;"  ::: "memory")

__device__ __forceinline__ uint32_t swz(uint32_t o) {   // 64B-row swizzle
    return o ^ ((o >> 3) & 0x30);
}
__device__ __forceinline__ void ldm4(uint32_t addr, uint32_t& r0, uint32_t& r1,
                                     uint32_t& r2, uint32_t& r3) {
    asm volatile("ldmatrix.sync.aligned.m8n8.x4.shared.b16 {%0,%1,%2,%3}, [%4];"
                 : "=r"(r0), "=r"(r1), "=r"(r2), "=r"(r3) : "r"(addr));
}
__device__ __forceinline__ void mma16816(float* d, const uint32_t* a,
                                         const uint32_t* b) {
    asm volatile(
        "mma.sync.aligned.m16n8k16.row.col.f32.bf16.bf16.f32 "
        "{%0,%1,%2,%3}, {%4,%5,%6,%7}, {%8,%9}, {%0,%1,%2,%3};"
        : "+f"(d[0]), "+f"(d[1]), "+f"(d[2]), "+f"(d[3])
        : "r"(a[0]), "r"(a[1]), "r"(a[2]), "r"(a[3]), "r"(b[0]), "r"(b[1]));
}
__device__ __forceinline__ void sts16(uint32_t addr, uint32_t r0, uint32_t r1,
                                      uint32_t r2, uint32_t r3) {
    asm volatile("st.shared.v4.b32 [%0], {%1,%2,%3,%4};"
                 :: "r"(addr), "r"(r0), "r"(r1), "r"(r2), "r"(r3) : "memory");
}

// 4 floats -> hi bf16x2 pair + lo bf16x2 pair
__device__ __forceinline__ void pack_hilo(float4 v, uint32_t& h0, uint32_t& h1,
                                          uint32_t& l0, uint32_t& l1) {
    __nv_bfloat16 a = __float2bfloat16(v.x), b = __float2bfloat16(v.y);
    __nv_bfloat16 c = __float2bfloat16(v.z), d = __float2bfloat16(v.w);
    __nv_bfloat16 e = __float2bfloat16(v.x - __bfloat162float(a));
    __nv_bfloat16 f = __float2bfloat16(v.y - __bfloat162float(b));
    __nv_bfloat16 g = __float2bfloat16(v.z - __bfloat162float(c));
    __nv_bfloat16 h = __float2bfloat16(v.w - __bfloat162float(d));
    __nv_bfloat162 hh0(a, b), hh1(c, d), ll0(e, f), ll1(g, h);
    h0 = *(uint32_t*)&hh0; h1 = *(uint32_t*)&hh1;
    l0 = *(uint32_t*)&ll0; l1 = *(uint32_t*)&ll1;
}
__device__ __forceinline__ void packh4(float4 v, uint32_t& h0, uint32_t& h1) {
    __nv_bfloat162 p0(__float2bfloat16(v.x), __float2bfloat16(v.y));
    __nv_bfloat162 p1(__float2bfloat16(v.z), __float2bfloat16(v.w));
    h0 = *(uint32_t*)&p0; h1 = *(uint32_t*)&p1;
}

// ---------------- dtype detection + count zeroing ----------------------------
__global__ void k_detect(const int* label, const int* lb) {
    __shared__ int nz_la, nz_lb;
    int t = threadIdx.x;
    if (t == 0) { nz_la = 0; nz_lb = 0; }
    __syncthreads();
    if (t < 64) {
        int w = 2 * (t * 128) + 1;
        if (label[w] != 0) atomicOr(&nz_la, 1);
        if (lb[w]    != 0) atomicOr(&nz_lb, 1);
    }
    __syncthreads();
    if (t == 0) g_is64 = (nz_la ? 0 : 1) | (nz_lb ? 0 : 2);
    for (int i = t; i < NSEG; i += blockDim.x) g_cnt[i] = 0;
}
__device__ __forceinline__ int ld_idx(const int* p, int i, bool is64) {
    return is64 ? p[2 * i] : p[i];
}

// ---------------- seg ids, counts, batch boundaries --------------------------
__global__ void k_prep(const int* label, const int* lb) {
    bool la64 = (g_is64 & 1) != 0, lb64 = (g_is64 & 2) != 0;
    int i = blockIdx.x * blockDim.x + threadIdx.x;
    if (i < N_) {
        int la = ld_idx(label, i, la64);
        int b  = ld_idx(lb,    i, lb64);
        int s  = b * NL + la;
        g_seg[i] = s;
        atomicAdd(&g_cnt[s], 1);
    }
    if (blockIdx.x == 0 && threadIdx.x <= NB) {
        int target = threadIdx.x;
        int lo = 0, hi = N_;
        while (lo < hi) {
            int mid = (lo + hi) >> 1;
            if (ld_idx(lb, mid, lb64) < target) lo = mid + 1; else hi = mid;
        }
        g_bstart[target] = lo;
    }
}

// ---------------- prefix scan over seg counts --------------------------------
__global__ void k_scan() {
    __shared__ int sh[1024];
    int t = threadIdx.x;
    int base = t * 4;
    int c[4];
    #pragma unroll
    for (int i = 0; i < 4; i++) c[i] = (base + i < NSEG) ? g_cnt[base + i] : 0;
    int tot = c[0] + c[1] + c[2] + c[3];
    sh[t] = tot;
    __syncthreads();
    int run = tot;
    for (int d = 1; d < 1024; d <<= 1) {
        int v = (t >= d) ? sh[t - d] : 0;
        __syncthreads();
        run += v; sh[t] = run;
        __syncthreads();
    }
    int excl = (t > 0) ? sh[t - 1] : 0;
    int p = excl;
    #pragma unroll
    for (int i = 0; i < 4; i++) {
        if (base + i <= NSEG) g_off[base + i] = p;
        if (base + i <  NSEG) g_cur[base + i] = p;
        p += c[i];
    }
}

// ---------------- scatter rows by segment ------------------------------------
__global__ void k_scatter() {
    int i = blockIdx.x * blockDim.x + threadIdx.x;
    int s = g_seg[i];
    int pos = atomicAdd(&g_cur[s], 1);
    g_rows[pos] = i;
}

// ---------------- weight hi/lo conversion ------------------------------------
__global__ void k_convw(const float* __restrict__ W1, const float* __restrict__ W2,
                        const float* __restrict__ b1, const float* __restrict__ b2) {
    int i = blockIdx.x * blockDim.x + threadIdx.x;   // float4 index over 512x2048
    int e = i * 4;
    int row = e >> 11;
    int col = e & 2047;
    const float* src = (row < 256) ? (W1 + (size_t)row * D_ + col)
                                   : (W2 + (size_t)(row - 256) * D_ + col);
    float4 v = *(const float4*)src;
    uint32_t h0, h1, l0, l1;
    pack_hilo(v, h0, h1, l0, l1);
    ((uint2*)g_bhi)[i] = make_uint2(h0, h1);
    ((uint2*)g_blo)[i] = make_uint2(l0, l1);
    if (blockIdx.x == 0 && threadIdx.x < P_)
        g_bias[threadIdx.x] = b1[threadIdx.x] + b2[threadIdx.x];
}

// ---------------- segment sums: sorted float4 gather, register acc ------------
// grid (D/64, NSEG/16), block 256 = 16 col4-slices x 16 segments.
__global__ void k_segsum(const float* __restrict__ x) {
    int c0   = blockIdx.x * 64;
    int s    = blockIdx.y * 16 + (threadIdx.x >> 4);
    int col4 = (threadIdx.x & 15) * 4;
    int i0 = g_off[s], i1 = g_off[s + 1];
    float4 a0 = make_float4(0.f, 0.f, 0.f, 0.f);
    float4 a1 = make_float4(0.f, 0.f, 0.f, 0.f);
    int i = i0;
    for (; i + 2 <= i1; i += 2) {
        int r0 = g_rows[i], r1 = g_rows[i + 1];
        float4 v0 = *(const float4*)(x + (size_t)r0 * D_ + c0 + col4);
        float4 v1 = *(const float4*)(x + (size_t)r1 * D_ + c0 + col4);
        a0.x += v0.x; a0.y += v0.y; a0.z += v0.z; a0.w += v0.w;
        a1.x += v1.x; a1.y += v1.y; a1.z += v1.z; a1.w += v1.w;
    }
    if (i < i1) {
        float4 v = *(const float4*)(x + (size_t)g_rows[i] * D_ + c0 + col4);
        a0.x += v.x; a0.y += v.y; a0.z += v.z; a0.w += v.w;
    }
    float4 r = make_float4(a0.x + a1.x, a0.y + a1.y, a0.z + a1.z, a0.w + a1.w);
    *(float4*)(g_sumx + (size_t)s * D_ + c0 + col4) = r;
}

// =============== main GEMM: out = x @ W1^T (3-term bf16) + M[seg] ============
// CTA tile 64(M) x 128(N), BK=32, 256 threads, warp grid 2x4 (tile 32x32).
// Stage: A_hi 4K | A_lo 4K | B_hi 8K | B_lo 8K = 24KB.  NST=3 -> 72KB.
#define STAGE_B 24576
#define SMEM_REQ (NST * STAGE_B)

__device__ __forceinline__ void ldgA(const float* __restrict__ Arows, int kt,
                                     int tid, float4* areg) {
    int row = tid >> 2, h = tid & 3;                 // 4 thr/row, 8 floats each
    const float4* p = (const float4*)(Arows + (size_t)row * D_ + (kt << 5) + h * 8);
    areg[0] = p[0]; areg[1] = p[1];
}
__device__ __forceinline__ void stsA(uint32_t sg, int tid, const float4* areg) {
    int row = tid >> 2, h = tid & 3;
    uint32_t h0a, h1a, l0a, l1a, h0b, h1b, l0b, l1b;
    pack_hilo(areg[0], h0a, h1a, l0a, l1a);
    pack_hilo(areg[1], h0b, h1b, l0b, l1b);
    uint32_t o = swz(row * 64 + h * 16);
    sts16(sg + o,        h0a, h1a, h0b, h1b);        // A_hi
    sts16(sg + 4096 + o, l0a, l1a, l0b, l1b);        // A_lo
}
__device__ __forceinline__ void ldB(const __nv_bfloat16* Bh, const __nv_bfloat16* Bl,
                                    int kt, uint32_t sg, int tid) {
    int k0 = kt << 5;
    const char* gBh = (const char*)(Bh + k0);
    const char* gBl = (const char*)(Bl + k0);
    #pragma unroll
    for (int i = 0; i < 2; i++) {
        int idx = i * 256 + tid;
        int row = idx >> 2, c = idx & 3;
        uint32_t off = swz(row * 64 + c * 16);
        cp16(sg + 8192  + off, gBh + (size_t)row * (D_ * 2) + c * 16);
        cp16(sg + 16384 + off, gBl + (size_t)row * (D_ * 2) + c * 16);
    }
}

__global__ void __launch_bounds__(256, 3) k_gemm(const float* __restrict__ x,
                                                 float* __restrict__ out) {
    extern __shared__ __align__(128) char smem[];
    uint32_t sbase = smem_u32(smem);
    int tid = threadIdx.x, lane = tid & 31, wid = tid >> 5;
    int wm = wid & 1, wn = wid >> 1;                 // warp grid 2(M) x 4(N)
    int n0 = blockIdx.x * 128, m0 = blockIdx.y * 64;
    const float* Arows = x + (size_t)m0 * D_;
    const __nv_bfloat16* Bh = g_bhi + (size_t)n0 * D_;
    const __nv_bfloat16* Bl = g_blo + (size_t)n0 * D_;
    const int ktn = 64;

    float d[2][4][4];
    #pragma unroll
    for (int i = 0; i < 2; i++)
        #pragma unroll
        for (int j = 0; j < 4; j++)
            #pragma unroll
            for (int k = 0; k < 4; k++) d[i][j][k] = 0.0f;

    float4 areg[2];
    ldgA(Arows, 0, tid, areg);
    stsA(sbase, tid, areg);
    ldB(Bh, Bl, 0, sbase, tid); CP_COMMIT();
    ldgA(Arows, 1, tid, areg);
    ldB(Bh, Bl, 1, sbase + STAGE_B, tid); CP_COMMIT();

    uint32_t aoff[2], boff[2];
    #pragma unroll
    for (int s = 0; s < 2; s++) {
        int arow = wm * 32 + (lane & 15);
        int acol = s * 32 + (lane >> 4) * 16;
        aoff[s] = swz(arow * 64 + acol);
        int brow = wn * 32 + ((lane >> 4) & 1) * 8 + (lane & 7);
        int bcol = s * 32 + ((lane >> 3) & 1) * 16;
        boff[s] = swz(brow * 64 + bcol);
    }

    for (int kt = 0; kt < ktn; kt++) {
        CP_WAIT1();
        __syncthreads();
        if (kt + 1 < ktn)
            stsA(sbase + ((kt + 1) % NST) * STAGE_B, tid, areg);
        if (kt + 2 < ktn) {
            ldgA(Arows, kt + 2, tid, areg);
            ldB(Bh, Bl, kt + 2, sbase + ((kt + 2) % NST) * STAGE_B, tid);
        }
        CP_COMMIT();

        uint32_t sAh = sbase + (kt % NST) * STAGE_B;
        uint32_t sAl = sAh + 4096;
        uint32_t sBh = sAh + 8192;
        uint32_t sBl = sAh + 16384;
        #pragma unroll
        for (int s = 0; s < 2; s++) {
            // batch ALL fragment loads first (MLP 8 on shared pipe),
            // then run the 24 dependency-free MMAs.
            uint32_t ah[2][4], al[2][4], bh[4][2], bl[4][2];
            #pragma unroll
            for (int f = 0; f < 2; f++)
                ldm4(sAh + f * 1024 + aoff[s], ah[f][0], ah[f][1], ah[f][2], ah[f][3]);
            #pragma unroll
            for (int p = 0; p < 2; p++)
                ldm4(sBh + p * 1024 + boff[s],
                     bh[2 * p][0], bh[2 * p][1], bh[2 * p + 1][0], bh[2 * p + 1][1]);
            #pragma unroll
            for (int p = 0; p < 2; p++)
                ldm4(sBl + p * 1024 + boff[s],
                     bl[2 * p][0], bl[2 * p][1], bl[2 * p + 1][0], bl[2 * p + 1][1]);
            #pragma unroll
            for (int f = 0; f < 2; f++)
                ldm4(sAl + f * 1024 + aoff[s], al[f][0], al[f][1], al[f][2], al[f][3]);
            #pragma unroll
            for (int mf = 0; mf < 2; mf++)
                #pragma unroll
                for (int nf = 0; nf < 4; nf++)
                    mma16816(d[mf][nf], ah[mf], bh[nf]);
            #pragma unroll
            for (int mf = 0; mf < 2; mf++)
                #pragma unroll
                for (int nf = 0; nf < 4; nf++)
                    mma16816(d[mf][nf], ah[mf], bl[nf]);
            #pragma unroll
            for (int mf = 0; mf < 2; mf++)
                #pragma unroll
                for (int nf = 0; nf < 4; nf++)
                    mma16816(d[mf][nf], al[mf], bh[nf]);
        }
    }
    CP_WAIT0();

    // epilogue: add per-segment mean addend (g_M includes both biases)
    #pragma unroll
    for (int mf = 0; mf < 2; mf++) {
        int r0 = m0 + wm * 32 + mf * 16 + (lane >> 2);
        int s0 = g_seg[r0], s1 = g_seg[r0 + 8];
        #pragma unroll
        for (int nf = 0; nf < 4; nf++) {
            int c = n0 + wn * 32 + nf * 8 + (lane & 3) * 2;
            float2 M0 = *(const float2*)(g_M + (size_t)s0 * P_ + c);
            float2 M1 = *(const float2*)(g_M + (size_t)s1 * P_ + c);
            *(float2*)(out + (size_t)r0 * P_ + c)
                = make_float2(d[mf][nf][0] + M0.x, d[mf][nf][1] + M0.y);
            *(float2*)(out + (size_t)(r0 + 8) * P_ + c)
                = make_float2(d[mf][nf][2] + M1.x, d[mf][nf][3] + M1.y);
        }
    }
}

// =============== mean GEMM: g_mpart[ks] = segsum_x @ W2^T (1-term bf16) ======
// CTA 64x128, BK=32 bf16, K-split 4 (512 each, 16 tiles).
#define MSTAGE_B 12288
#define MSMEM_REQ (NST * MSTAGE_B)

__device__ __forceinline__ void stsA1(uint32_t sg, int tid, const float4* areg) {
    int row = tid >> 2, h = tid & 3;
    uint32_t h0, h1, h2, h3;
    packh4(areg[0], h0, h1);
    packh4(areg[1], h2, h3);
    sts16(sg + swz(row * 64 + h * 16), h0, h1, h2, h3);
}
__device__ __forceinline__ void ldB1(const char* Bh, int kt, uint32_t sg, int tid) {
    int k0 = kt << 6;   // bytes
    #pragma unroll
    for (int i = 0; i < 2; i++) {
        int idx = i * 256 + tid;
        int row = idx >> 2, c = idx & 3;
        uint32_t off = swz(row * 64 + c * 16);
        cp16(sg + 4096 + off, Bh + (size_t)row * (D_ * 2) + k0 + c * 16);
    }
}

__global__ void __launch_bounds__(256, 3) k_mgemm() {
    extern __shared__ __align__(128) char smem[];
    uint32_t sbase = smem_u32(smem);
    int tid = threadIdx.x, lane = tid & 31, wid = tid >> 5;
    int wm = wid & 1, wn = wid >> 1;
    int n0 = blockIdx.x * 128, m0 = blockIdx.y * 64, ks = blockIdx.z;
    const float* Arows = g_sumx + (size_t)m0 * D_ + ks * 512;
    const char*  Bh    = (const char*)(g_bhi + (size_t)(256 + n0) * D_ + ks * 512);
    float* dst = g_mpart + (size_t)ks * NSEG * P_ + (size_t)m0 * P_ + n0;
    const int ktn = 16;

    float d[2][4][4];
    #pragma unroll
    for (int i = 0; i < 2; i++)
        #pragma unroll
        for (int j = 0; j < 4; j++)
            #pragma unroll
            for (int k = 0; k < 4; k++) d[i][j][k] = 0.0f;

    float4 areg[2];
    ldgA(Arows, 0, tid, areg);
    stsA1(sbase, tid, areg);
    ldB1(Bh, 0, sbase, tid); CP_COMMIT();
    ldgA(Arows, 1, tid, areg);
    ldB1(Bh, 1, sbase + MSTAGE_B, tid); CP_COMMIT();

    uint32_t aoff[2], boff[2];
    #pragma unroll
    for (int s = 0; s < 2; s++) {
        int arow = wm * 32 + (lane & 15);
        int acol = s * 32 + (lane >> 4) * 16;
        aoff[s] = swz(arow * 64 + acol);
        int brow = wn * 32 + ((lane >> 4) & 1) * 8 + (lane & 7);
        int bcol = s * 32 + ((lane >> 3) & 1) * 16;
        boff[s] = swz(brow * 64 + bcol);
    }

    for (int kt = 0; kt < ktn; kt++) {
        CP_WAIT1();
        __syncthreads();
        if (kt + 1 < ktn)
            stsA1(sbase + ((kt + 1) % NST) * MSTAGE_B, tid, areg);
        if (kt + 2 < ktn) {
            ldgA(Arows, kt + 2, tid, areg);
            ldB1(Bh, kt + 2, sbase + ((kt + 2) % NST) * MSTAGE_B, tid);
        }
        CP_COMMIT();

        uint32_t sA = sbase + (kt % NST) * MSTAGE_B;
        uint32_t sB = sA + 4096;
        #pragma unroll
        for (int s = 0; s < 2; s++) {
            uint32_t a[2][4], b[4][2];
            #pragma unroll
            for (int f = 0; f < 2; f++)
                ldm4(sA + f * 1024 + aoff[s], a[f][0], a[f][1], a[f][2], a[f][3]);
            #pragma unroll
            for (int p = 0; p < 2; p++)
                ldm4(sB + p * 1024 + boff[s],
                     b[2 * p][0], b[2 * p][1], b[2 * p + 1][0], b[2 * p + 1][1]);
            #pragma unroll
            for (int mf = 0; mf < 2; mf++)
                #pragma unroll
                for (int nf = 0; nf < 4; nf++)
                    mma16816(d[mf][nf], a[mf], b[nf]);
        }
    }
    CP_WAIT0();

    #pragma unroll
    for (int mf = 0; mf < 2; mf++) {
        #pragma unroll
        for (int nf = 0; nf < 4; nf++) {
            int r = wm * 32 + mf * 16 + (lane >> 2);
            int c = wn * 32 + nf * 8 + (lane & 3) * 2;
            *(float2*)(dst + (size_t)r * P_ + c)
                = make_float2(d[mf][nf][0], d[mf][nf][1]);
            *(float2*)(dst + (size_t)(r + 8) * P_ + c)
                = make_float2(d[mf][nf][2], d[mf][nf][3]);
        }
    }
}

// ---------------- reduce K-split parts ---------------------------------------
__global__ void k_mred() {
    int i = blockIdx.x * blockDim.x + threadIdx.x;
    float s = g_mpart[i] + g_mpart[NSEG * P_ + i]
            + g_mpart[2 * NSEG * P_ + i] + g_mpart[3 * NSEG * P_ + i];
    g_sum_bl2[i] = s;
}

// ---------------- per-batch sums from per-seg sums ---------------------------
__global__ void k_sumb() {
    int b = blockIdx.x, h = blockIdx.y;
    int col = h * 128 + threadIdx.x;
    const float* base = g_sum_bl2 + (size_t)(b * NL) * P_ + col;
    float acc = 0.0f;
    #pragma unroll 4
    for (int l = 0; l < NL; l++) acc += base[(size_t)l * P_];
    g_sum_b2[b * P_ + col] = acc;
}

// ---------------- per-segment output addend ----------------------------------
__global__ void k_minv() {
    int s = blockIdx.x, t = threadIdx.x;
    int b = s / NL;
    int cb = g_bstart[b + 1] - g_bstart[b];
    int d = cb - g_cnt[s];
    float inv = (d > 0) ? (1.0f / (float)d) : 0.0f;
    float m = (g_sum_b2[b * P_ + t] - g_sum_bl2[(size_t)s * P_ + t]) * inv;
    g_M[(size_t)s * P_ + t] = m + g_bias[t];
}

// ---------------- launch -----------------------------------------------------
extern "C" void kernel_launch(void* const* d_in, const int* in_sizes, int n_in,
                              void* d_out, int out_size) {
    const float* x     = (const float*)d_in[0];
    const int*   label = (const int*)  d_in[1];
    const int*   lb    = (const int*)  d_in[2];
    const float* W1_w  = (const float*)d_in[3];
    const float* W1_b  = (const float*)d_in[4];
    const float* W2_w  = (const float*)d_in[5];
    const float* W2_b  = (const float*)d_in[6];
    float* out = (float*)d_out;

    cudaFuncSetAttribute(k_gemm,  cudaFuncAttributeMaxDynamicSharedMemorySize, SMEM_REQ);
    cudaFuncSetAttribute(k_mgemm, cudaFuncAttributeMaxDynamicSharedMemorySize, MSMEM_REQ);

    k_convw<<<(512 * D_ / 4) / 256, 256>>>(W1_w, W2_w, W1_b, W2_b);
    k_detect<<<1, 256>>>(label, lb);
    k_prep<<<N_ / 256, 256>>>(label, lb);
    k_scan<<<1, 1024>>>();
    k_scatter<<<N_ / 256, 256>>>();
    k_segsum<<<dim3(D_ / 64, NSEG / 16), 256>>>(x);
    k_mgemm<<<dim3(2, NSEG / 64, 4), 256, MSMEM_REQ>>>();
    k_mred<<<(NSEG * P_) / 256, 256>>>();
    k_sumb<<<dim3(NB, 2), 128>>>();
    k_minv<<<NSEG, 256>>>();
    k_gemm<<<dim3(2, 256), 256, SMEM_REQ>>>(x, out);
}

// round 12
// speedup vs baseline: 4.4105x; 1.2492x over previous
#include <cuda_runtime.h>
#include <cuda_bf16.h>
#include <cstdint>

#define N_   16384
#define D_   2048
#define P_   256
#define NB   32
#define NL   100
#define NSEG (NB*NL)
#define NST  3          // pipeline stages

// ---------------- scratch globals (no allocations allowed) -------------------
__device__ __nv_bfloat16 g_bhi[512 * D_];   // [W1;W2] hi
__device__ __nv_bfloat16 g_blo[512 * D_];   // [W1;W2] lo (W2 half unused)
__device__ float g_sumx[NSEG * D_];         // exact fp32 segsum of x
__device__ float g_mpart[4 * NSEG * P_];    // K-split partials of segsum@W2^T
__device__ float g_sum_bl2[NSEG * P_];
__device__ float g_sum_b2 [NB   * P_];
__device__ float g_M[NSEG * P_];
__device__ float g_bias[P_];
__device__ int   g_cnt[NSEG];
__device__ int   g_off[NSEG + 1];
__device__ int   g_cur[NSEG];
__device__ int   g_rows[N_];
__device__ int   g_seg[N_];
__device__ int   g_bstart[NB + 1];
__device__ int   g_is64;

// ---------------- PTX helpers ------------------------------------------------
__device__ __forceinline__ uint32_t smem_u32(const void* p) {
    uint32_t a;
    asm("{ .reg .u64 t; cvta.to.shared.u64 t, %1; cvt.u32.u64 %0, t; }" : "=r"(a) : "l"(p));
    return a;
}
__device__ __forceinline__ void cp16(uint32_t dst, const void* src) {
    asm volatile("cp.async.cg.shared.global [%0], [%1], 16;" :: "r"(dst), "l"(src));
}
#define CP_COMMIT() asm volatile("cp.async.commit_group;" ::: "memory")
#define CP_WAIT1()  asm volatile("cp.async.wait_group 1;"  ::: "memory")
#define CP_WAIT0()  asm volatile("cp.async.wait_group 0;"  ::: "memory")

__device__ __forceinline__ uint32_t swz(uint32_t o) {   // 64B-row swizzle
    return o ^ ((o >> 3) & 0x30);
}
__device__ __forceinline__ void ldm4(uint32_t addr, uint32_t& r0, uint32_t& r1,
                                     uint32_t& r2, uint32_t& r3) {
    asm volatile("ldmatrix.sync.aligned.m8n8.x4.shared.b16 {%0,%1,%2,%3}, [%4];"
                 : "=r"(r0), "=r"(r1), "=r"(r2), "=r"(r3) : "r"(addr));
}
__device__ __forceinline__ void mma16816(float* d, const uint32_t* a,
                                         const uint32_t* b) {
    asm volatile(
        "mma.sync.aligned.m16n8k16.row.col.f32.bf16.bf16.f32 "
        "{%0,%1,%2,%3}, {%4,%5,%6,%7}, {%8,%9}, {%0,%1,%2,%3};"
        : "+f"(d[0]), "+f"(d[1]), "+f"(d[2]), "+f"(d[3])
        : "r"(a[0]), "r"(a[1]), "r"(a[2]), "r"(a[3]), "r"(b[0]), "r"(b[1]));
}
__device__ __forceinline__ void sts16(uint32_t addr, uint32_t r0, uint32_t r1,
                                      uint32_t r2, uint32_t r3) {
    asm volatile("st.shared.v4.b32 [%0], {%1,%2,%3,%4};"
                 :: "r"(addr), "r"(r0), "r"(r1), "r"(r2), "r"(r3) : "memory");
}

// 4 floats -> hi bf16x2 pair + lo bf16x2 pair
__device__ __forceinline__ void pack_hilo(float4 v, uint32_t& h0, uint32_t& h1,
                                          uint32_t& l0, uint32_t& l1) {
    __nv_bfloat16 a = __float2bfloat16(v.x), b = __float2bfloat16(v.y);
    __nv_bfloat16 c = __float2bfloat16(v.z), d = __float2bfloat16(v.w);
    __nv_bfloat16 e = __float2bfloat16(v.x - __bfloat162float(a));
    __nv_bfloat16 f = __float2bfloat16(v.y - __bfloat162float(b));
    __nv_bfloat16 g = __float2bfloat16(v.z - __bfloat162float(c));
    __nv_bfloat16 h = __float2bfloat16(v.w - __bfloat162float(d));
    __nv_bfloat162 hh0(a, b), hh1(c, d), ll0(e, f), ll1(g, h);
    h0 = *(uint32_t*)&hh0; h1 = *(uint32_t*)&hh1;
    l0 = *(uint32_t*)&ll0; l1 = *(uint32_t*)&ll1;
}
__device__ __forceinline__ void packh4(float4 v, uint32_t& h0, uint32_t& h1) {
    __nv_bfloat162 p0(__float2bfloat16(v.x), __float2bfloat16(v.y));
    __nv_bfloat162 p1(__float2bfloat16(v.z), __float2bfloat16(v.w));
    h0 = *(uint32_t*)&p0; h1 = *(uint32_t*)&p1;
}

// ---------------- dtype detection + count zeroing ----------------------------
__global__ void k_detect(const int* label, const int* lb) {
    __shared__ int nz_la, nz_lb;
    int t = threadIdx.x;
    if (t == 0) { nz_la = 0; nz_lb = 0; }
    __syncthreads();
    if (t < 64) {
        int w = 2 * (t * 128) + 1;
        if (label[w] != 0) atomicOr(&nz_la, 1);
        if (lb[w]    != 0) atomicOr(&nz_lb, 1);
    }
    __syncthreads();
    if (t == 0) g_is64 = (nz_la ? 0 : 1) | (nz_lb ? 0 : 2);
    for (int i = t; i < NSEG; i += blockDim.x) g_cnt[i] = 0;
}
__device__ __forceinline__ int ld_idx(const int* p, int i, bool is64) {
    return is64 ? p[2 * i] : p[i];
}

// ---------------- seg ids, counts, batch boundaries --------------------------
__global__ void k_prep(const int* label, const int* lb) {
    bool la64 = (g_is64 & 1) != 0, lb64 = (g_is64 & 2) != 0;
    int i = blockIdx.x * blockDim.x + threadIdx.x;
    if (i < N_) {
        int la = ld_idx(label, i, la64);
        int b  = ld_idx(lb,    i, lb64);
        int s  = b * NL + la;
        g_seg[i] = s;
        atomicAdd(&g_cnt[s], 1);
    }
    if (blockIdx.x == 0 && threadIdx.x <= NB) {
        int target = threadIdx.x;
        int lo = 0, hi = N_;
        while (lo < hi) {
            int mid = (lo + hi) >> 1;
            if (ld_idx(lb, mid, lb64) < target) lo = mid + 1; else hi = mid;
        }
        g_bstart[target] = lo;
    }
}

// ---------------- prefix scan over seg counts --------------------------------
__global__ void k_scan() {
    __shared__ int sh[1024];
    int t = threadIdx.x;
    int base = t * 4;
    int c[4];
    #pragma unroll
    for (int i = 0; i < 4; i++) c[i] = (base + i < NSEG) ? g_cnt[base + i] : 0;
    int tot = c[0] + c[1] + c[2] + c[3];
    sh[t] = tot;
    __syncthreads();
    int run = tot;
    for (int d = 1; d < 1024; d <<= 1) {
        int v = (t >= d) ? sh[t - d] : 0;
        __syncthreads();
        run += v; sh[t] = run;
        __syncthreads();
    }
    int excl = (t > 0) ? sh[t - 1] : 0;
    int p = excl;
    #pragma unroll
    for (int i = 0; i < 4; i++) {
        if (base + i <= NSEG) g_off[base + i] = p;
        if (base + i <  NSEG) g_cur[base + i] = p;
        p += c[i];
    }
}

// ---------------- scatter rows by segment ------------------------------------
__global__ void k_scatter() {
    int i = blockIdx.x * blockDim.x + threadIdx.x;
    int s = g_seg[i];
    int pos = atomicAdd(&g_cur[s], 1);
    g_rows[pos] = i;
}

// ---------------- weight hi/lo conversion ------------------------------------
__global__ void k_convw(const float* __restrict__ W1, const float* __restrict__ W2,
                        const float* __restrict__ b1, const float* __restrict__ b2) {
    int i = blockIdx.x * blockDim.x + threadIdx.x;   // float4 index over 512x2048
    int e = i * 4;
    int row = e >> 11;
    int col = e & 2047;
    const float* src = (row < 256) ? (W1 + (size_t)row * D_ + col)
                                   : (W2 + (size_t)(row - 256) * D_ + col);
    float4 v = *(const float4*)src;
    uint32_t h0, h1, l0, l1;
    pack_hilo(v, h0, h1, l0, l1);
    ((uint2*)g_bhi)[i] = make_uint2(h0, h1);
    ((uint2*)g_blo)[i] = make_uint2(l0, l1);
    if (blockIdx.x == 0 && threadIdx.x < P_)
        g_bias[threadIdx.x] = b1[threadIdx.x] + b2[threadIdx.x];
}

// ---------------- segment sums: sorted float4 gather, register acc ------------
__global__ void k_segsum(const float* __restrict__ x) {
    int c0   = blockIdx.x * 64;
    int s    = blockIdx.y * 16 + (threadIdx.x >> 4);
    int col4 = (threadIdx.x & 15) * 4;
    int i0 = g_off[s], i1 = g_off[s + 1];
    float4 a0 = make_float4(0.f, 0.f, 0.f, 0.f);
    float4 a1 = make_float4(0.f, 0.f, 0.f, 0.f);
    int i = i0;
    for (; i + 2 <= i1; i += 2) {
        int r0 = g_rows[i], r1 = g_rows[i + 1];
        float4 v0 = *(const float4*)(x + (size_t)r0 * D_ + c0 + col4);
        float4 v1 = *(const float4*)(x + (size_t)r1 * D_ + c0 + col4);
        a0.x += v0.x; a0.y += v0.y; a0.z += v0.z; a0.w += v0.w;
        a1.x += v1.x; a1.y += v1.y; a1.z += v1.z; a1.w += v1.w;
    }
    if (i < i1) {
        float4 v = *(const float4*)(x + (size_t)g_rows[i] * D_ + c0 + col4);
        a0.x += v.x; a0.y += v.y; a0.z += v.z; a0.w += v.w;
    }
    float4 r = make_float4(a0.x + a1.x, a0.y + a1.y, a0.z + a1.z, a0.w + a1.w);
    *(float4*)(g_sumx + (size_t)s * D_ + c0 + col4) = r;
}

// =============== main GEMM: out = x @ W1^T (3-term bf16), plain store ========
#define STAGE_B 24576
#define SMEM_REQ (NST * STAGE_B)

__device__ __forceinline__ void ldgA(const float* __restrict__ Arows, int kt,
                                     int tid, float4* areg) {
    int row = tid >> 2, h = tid & 3;                 // 4 thr/row, 8 floats each
    const float4* p = (const float4*)(Arows + (size_t)row * D_ + (kt << 5) + h * 8);
    areg[0] = p[0]; areg[1] = p[1];
}
__device__ __forceinline__ void stsA(uint32_t sg, int tid, const float4* areg) {
    int row = tid >> 2, h = tid & 3;
    uint32_t h0a, h1a, l0a, l1a, h0b, h1b, l0b, l1b;
    pack_hilo(areg[0], h0a, h1a, l0a, l1a);
    pack_hilo(areg[1], h0b, h1b, l0b, l1b);
    uint32_t o = swz(row * 64 + h * 16);
    sts16(sg + o,        h0a, h1a, h0b, h1b);        // A_hi
    sts16(sg + 4096 + o, l0a, l1a, l0b, l1b);        // A_lo
}
__device__ __forceinline__ void ldB(const __nv_bfloat16* Bh, const __nv_bfloat16* Bl,
                                    int kt, uint32_t sg, int tid) {
    int k0 = kt << 5;
    const char* gBh = (const char*)(Bh + k0);
    const char* gBl = (const char*)(Bl + k0);
    #pragma unroll
    for (int i = 0; i < 2; i++) {
        int idx = i * 256 + tid;
        int row = idx >> 2, c = idx & 3;
        uint32_t off = swz(row * 64 + c * 16);
        cp16(sg + 8192  + off, gBh + (size_t)row * (D_ * 2) + c * 16);
        cp16(sg + 16384 + off, gBl + (size_t)row * (D_ * 2) + c * 16);
    }
}

__global__ void __launch_bounds__(256, 3) k_gemm(const float* __restrict__ x,
                                                 float* __restrict__ out) {
    extern __shared__ __align__(128) char smem[];
    uint32_t sbase = smem_u32(smem);
    int tid = threadIdx.x, lane = tid & 31, wid = tid >> 5;
    int wm = wid & 1, wn = wid >> 1;                 // warp grid 2(M) x 4(N)
    int n0 = blockIdx.x * 128, m0 = blockIdx.y * 64;
    const float* Arows = x + (size_t)m0 * D_;
    const __nv_bfloat16* Bh = g_bhi + (size_t)n0 * D_;
    const __nv_bfloat16* Bl = g_blo + (size_t)n0 * D_;
    const int ktn = 64;

    float d[2][4][4];
    #pragma unroll
    for (int i = 0; i < 2; i++)
        #pragma unroll
        for (int j = 0; j < 4; j++)
            #pragma unroll
            for (int k = 0; k < 4; k++) d[i][j][k] = 0.0f;

    float4 areg[2];
    ldgA(Arows, 0, tid, areg);
    stsA(sbase, tid, areg);
    ldB(Bh, Bl, 0, sbase, tid); CP_COMMIT();
    ldgA(Arows, 1, tid, areg);
    ldB(Bh, Bl, 1, sbase + STAGE_B, tid); CP_COMMIT();

    uint32_t aoff[2], boff[2];
    #pragma unroll
    for (int s = 0; s < 2; s++) {
        int arow = wm * 32 + (lane & 15);
        int acol = s * 32 + (lane >> 4) * 16;
        aoff[s] = swz(arow * 64 + acol);
        int brow = wn * 32 + ((lane >> 4) & 1) * 8 + (lane & 7);
        int bcol = s * 32 + ((lane >> 3) & 1) * 16;
        boff[s] = swz(brow * 64 + bcol);
    }

    for (int kt = 0; kt < ktn; kt++) {
        CP_WAIT1();
        __syncthreads();
        if (kt + 1 < ktn)
            stsA(sbase + ((kt + 1) % NST) * STAGE_B, tid, areg);
        if (kt + 2 < ktn) {
            ldgA(Arows, kt + 2, tid, areg);
            ldB(Bh, Bl, kt + 2, sbase + ((kt + 2) % NST) * STAGE_B, tid);
        }
        CP_COMMIT();

        uint32_t sAh = sbase + (kt % NST) * STAGE_B;
        uint32_t sAl = sAh + 4096;
        uint32_t sBh = sAh + 8192;
        uint32_t sBl = sAh + 16384;
        #pragma unroll
        for (int s = 0; s < 2; s++) {
            uint32_t ah[2][4], al[2][4], bh[4][2], bl[4][2];
            #pragma unroll
            for (int f = 0; f < 2; f++)
                ldm4(sAh + f * 1024 + aoff[s], ah[f][0], ah[f][1], ah[f][2], ah[f][3]);
            #pragma unroll
            for (int p = 0; p < 2; p++)
                ldm4(sBh + p * 1024 + boff[s],
                     bh[2 * p][0], bh[2 * p][1], bh[2 * p + 1][0], bh[2 * p + 1][1]);
            #pragma unroll
            for (int p = 0; p < 2; p++)
                ldm4(sBl + p * 1024 + boff[s],
                     bl[2 * p][0], bl[2 * p][1], bl[2 * p + 1][0], bl[2 * p + 1][1]);
            #pragma unroll
            for (int f = 0; f < 2; f++)
                ldm4(sAl + f * 1024 + aoff[s], al[f][0], al[f][1], al[f][2], al[f][3]);
            #pragma unroll
            for (int mf = 0; mf < 2; mf++)
                #pragma unroll
                for (int nf = 0; nf < 4; nf++)
                    mma16816(d[mf][nf], ah[mf], bh[nf]);
            #pragma unroll
            for (int mf = 0; mf < 2; mf++)
                #pragma unroll
                for (int nf = 0; nf < 4; nf++)
                    mma16816(d[mf][nf], ah[mf], bl[nf]);
            #pragma unroll
            for (int mf = 0; mf < 2; mf++)
                #pragma unroll
                for (int nf = 0; nf < 4; nf++)
                    mma16816(d[mf][nf], al[mf], bh[nf]);
        }
    }
    CP_WAIT0();

    // plain store; g_M added later by k_fixup (computed concurrently)
    #pragma unroll
    for (int mf = 0; mf < 2; mf++) {
        int r0 = m0 + wm * 32 + mf * 16 + (lane >> 2);
        #pragma unroll
        for (int nf = 0; nf < 4; nf++) {
            int c = n0 + wn * 32 + nf * 8 + (lane & 3) * 2;
            *(float2*)(out + (size_t)r0 * P_ + c)
                = make_float2(d[mf][nf][0], d[mf][nf][1]);
            *(float2*)(out + (size_t)(r0 + 8) * P_ + c)
                = make_float2(d[mf][nf][2], d[mf][nf][3]);
        }
    }
}

// =============== mean GEMM: g_mpart[ks] = segsum_x @ W2^T (1-term bf16) ======
#define MSTAGE_B 12288
#define MSMEM_REQ (NST * MSTAGE_B)

__device__ __forceinline__ void stsA1(uint32_t sg, int tid, const float4* areg) {
    int row = tid >> 2, h = tid & 3;
    uint32_t h0, h1, h2, h3;
    packh4(areg[0], h0, h1);
    packh4(areg[1], h2, h3);
    sts16(sg + swz(row * 64 + h * 16), h0, h1, h2, h3);
}
__device__ __forceinline__ void ldB1(const char* Bh, int kt, uint32_t sg, int tid) {
    int k0 = kt << 6;   // bytes
    #pragma unroll
    for (int i = 0; i < 2; i++) {
        int idx = i * 256 + tid;
        int row = idx >> 2, c = idx & 3;
        uint32_t off = swz(row * 64 + c * 16);
        cp16(sg + 4096 + off, Bh + (size_t)row * (D_ * 2) + k0 + c * 16);
    }
}

__global__ void __launch_bounds__(256, 3) k_mgemm() {
    extern __shared__ __align__(128) char smem[];
    uint32_t sbase = smem_u32(smem);
    int tid = threadIdx.x, lane = tid & 31, wid = tid >> 5;
    int wm = wid & 1, wn = wid >> 1;
    int n0 = blockIdx.x * 128, m0 = blockIdx.y * 64, ks = blockIdx.z;
    const float* Arows = g_sumx + (size_t)m0 * D_ + ks * 512;
    const char*  Bh    = (const char*)(g_bhi + (size_t)(256 + n0) * D_ + ks * 512);
    float* dst = g_mpart + (size_t)ks * NSEG * P_ + (size_t)m0 * P_ + n0;
    const int ktn = 16;

    float d[2][4][4];
    #pragma unroll
    for (int i = 0; i < 2; i++)
        #pragma unroll
        for (int j = 0; j < 4; j++)
            #pragma unroll
            for (int k = 0; k < 4; k++) d[i][j][k] = 0.0f;

    float4 areg[2];
    ldgA(Arows, 0, tid, areg);
    stsA1(sbase, tid, areg);
    ldB1(Bh, 0, sbase, tid); CP_COMMIT();
    ldgA(Arows, 1, tid, areg);
    ldB1(Bh, 1, sbase + MSTAGE_B, tid); CP_COMMIT();

    uint32_t aoff[2], boff[2];
    #pragma unroll
    for (int s = 0; s < 2; s++) {
        int arow = wm * 32 + (lane & 15);
        int acol = s * 32 + (lane >> 4) * 16;
        aoff[s] = swz(arow * 64 + acol);
        int brow = wn * 32 + ((lane >> 4) & 1) * 8 + (lane & 7);
        int bcol = s * 32 + ((lane >> 3) & 1) * 16;
        boff[s] = swz(brow * 64 + bcol);
    }

    for (int kt = 0; kt < ktn; kt++) {
        CP_WAIT1();
        __syncthreads();
        if (kt + 1 < ktn)
            stsA1(sbase + ((kt + 1) % NST) * MSTAGE_B, tid, areg);
        if (kt + 2 < ktn) {
            ldgA(Arows, kt + 2, tid, areg);
            ldB1(Bh, kt + 2, sbase + ((kt + 2) % NST) * MSTAGE_B, tid);
        }
        CP_COMMIT();

        uint32_t sA = sbase + (kt % NST) * MSTAGE_B;
        uint32_t sB = sA + 4096;
        #pragma unroll
        for (int s = 0; s < 2; s++) {
            uint32_t a[2][4], b[4][2];
            #pragma unroll
            for (int f = 0; f < 2; f++)
                ldm4(sA + f * 1024 + aoff[s], a[f][0], a[f][1], a[f][2], a[f][3]);
            #pragma unroll
            for (int p = 0; p < 2; p++)
                ldm4(sB + p * 1024 + boff[s],
                     b[2 * p][0], b[2 * p][1], b[2 * p + 1][0], b[2 * p + 1][1]);
            #pragma unroll
            for (int mf = 0; mf < 2; mf++)
                #pragma unroll
                for (int nf = 0; nf < 4; nf++)
                    mma16816(d[mf][nf], a[mf], b[nf]);
        }
    }
    CP_WAIT0();

    #pragma unroll
    for (int mf = 0; mf < 2; mf++) {
        #pragma unroll
        for (int nf = 0; nf < 4; nf++) {
            int r = wm * 32 + mf * 16 + (lane >> 2);
            int c = wn * 32 + nf * 8 + (lane & 3) * 2;
            *(float2*)(dst + (size_t)r * P_ + c)
                = make_float2(d[mf][nf][0], d[mf][nf][1]);
            *(float2*)(dst + (size_t)(r + 8) * P_ + c)
                = make_float2(d[mf][nf][2], d[mf][nf][3]);
        }
    }
}

// ---------------- reduce K-split parts ---------------------------------------
__global__ void k_mred() {
    int i = blockIdx.x * blockDim.x + threadIdx.x;
    float s = g_mpart[i] + g_mpart[NSEG * P_ + i]
            + g_mpart[2 * NSEG * P_ + i] + g_mpart[3 * NSEG * P_ + i];
    g_sum_bl2[i] = s;
}

// ---------------- per-batch sums from per-seg sums ---------------------------
__global__ void k_sumb() {
    int b = blockIdx.x, h = blockIdx.y;
    int col = h * 128 + threadIdx.x;
    const float* base = g_sum_bl2 + (size_t)(b * NL) * P_ + col;
    float acc = 0.0f;
    #pragma unroll 4
    for (int l = 0; l < NL; l++) acc += base[(size_t)l * P_];
    g_sum_b2[b * P_ + col] = acc;
}

// ---------------- per-segment output addend ----------------------------------
__global__ void k_minv() {
    int s = blockIdx.x, t = threadIdx.x;
    int b = s / NL;
    int cb = g_bstart[b + 1] - g_bstart[b];
    int d = cb - g_cnt[s];
    float inv = (d > 0) ? (1.0f / (float)d) : 0.0f;
    float m = (g_sum_b2[b * P_ + t] - g_sum_bl2[(size_t)s * P_ + t]) * inv;
    g_M[(size_t)s * P_ + t] = m + g_bias[t];
}

// ---------------- final gather-add -------------------------------------------
__global__ void k_fixup(float* __restrict__ out) {
    int i = blockIdx.x * blockDim.x + threadIdx.x;   // float4 index
    int row = i >> 6;
    int c4  = (i & 63) << 2;
    int s = g_seg[row];
    float4 o = *(float4*)(out + (size_t)row * P_ + c4);
    float4 m = *(const float4*)(g_M + (size_t)s * P_ + c4);
    o.x += m.x; o.y += m.y; o.z += m.z; o.w += m.w;
    *(float4*)(out + (size_t)row * P_ + c4) = o;
}

// ---------------- launch: two-stream fork/join inside graph capture ----------
extern "C" void kernel_launch(void* const* d_in, const int* in_sizes, int n_in,
                              void* d_out, int out_size) {
    const float* x     = (const float*)d_in[0];
    const int*   label = (const int*)  d_in[1];
    const int*   lb    = (const int*)  d_in[2];
    const float* W1_w  = (const float*)d_in[3];
    const float* W1_b  = (const float*)d_in[4];
    const float* W2_w  = (const float*)d_in[5];
    const float* W2_b  = (const float*)d_in[6];
    float* out = (float*)d_out;

    cudaFuncSetAttribute(k_gemm,  cudaFuncAttributeMaxDynamicSharedMemorySize, SMEM_REQ);
    cudaFuncSetAttribute(k_mgemm, cudaFuncAttributeMaxDynamicSharedMemorySize, MSMEM_REQ);

    cudaStream_t sB;
    cudaStreamCreateWithFlags(&sB, cudaStreamNonBlocking);
    cudaEvent_t evFork, evConvw, evB;
    cudaEventCreateWithFlags(&evFork,  cudaEventDisableTiming);
    cudaEventCreateWithFlags(&evConvw, cudaEventDisableTiming);
    cudaEventCreateWithFlags(&evB,     cudaEventDisableTiming);

    // fork aux stream from the capturing (default) stream
    cudaEventRecord(evFork, 0);
    cudaStreamWaitEvent(sB, evFork, 0);

    // ---- stream B: segment bookkeeping + mean pipeline ----
    k_detect <<<1, 256, 0, sB>>>(label, lb);
    k_prep   <<<N_ / 256, 256, 0, sB>>>(label, lb);
    k_scan   <<<1, 1024, 0, sB>>>();
    k_scatter<<<N_ / 256, 256, 0, sB>>>();
    k_segsum <<<dim3(D_ / 64, NSEG / 16), 256, 0, sB>>>(x);

    // ---- default stream: weight conversion, then main GEMM ----
    k_convw<<<(512 * D_ / 4) / 256, 256>>>(W1_w, W2_w, W1_b, W2_b);
    cudaEventRecord(evConvw, 0);
    cudaStreamWaitEvent(sB, evConvw, 0);   // mgemm needs g_bhi (W2 half) + g_bias

    k_mgemm<<<dim3(2, NSEG / 64, 4), 256, MSMEM_REQ, sB>>>();
    k_mred <<<(NSEG * P_) / 256, 256, 0, sB>>>();
    k_sumb <<<dim3(NB, 2), 128, 0, sB>>>();
    k_minv <<<NSEG, 256, 0, sB>>>();
    cudaEventRecord(evB, sB);

    k_gemm<<<dim3(2, 256), 256, SMEM_REQ>>>(x, out);

    // join: fixup needs both out (default) and g_M/g_seg (stream B)
    cudaStreamWaitEvent(0, evB, 0);
    k_fixup<<<(N_ * P_ / 4) / 256, 256>>>(out);
}